// round 13
// baseline (speedup 1.0000x reference)
#include <cuda_runtime.h>
#include <math.h>

#define HID    256
#define BS     64
#define DCS    16
#define NCLS   60
#define QSZ    5
#define TOPK   5
#define TOPKQ  100
#define NROWS  (BS * DCS)          // 1024
#define NKEYS  (NCLS * DCS)        // 960
#define CAND   (TOPK * QSZ * DCS)  // 400
#define CPB    (QSZ * DCS)         // 80
#define CAP    (NROWS * TOPK)      // 5120 max pairs per class
#define KSPLIT 4

// ---------------------------------------------------------------------------
// Scratch (float):
#define OFF_KEY   0
#define OFF_QRY   (OFF_KEY  + NKEYS*HID)
#define OFF_QHAT  (OFF_QRY  + NROWS*HID)
#define OFF_KEYP  (OFF_QHAT + NROWS*HID)
#define OFF_SC1   (OFF_KEYP + NKEYS*HID)
#define OFF_SC2   (OFF_SC1  + NROWS*NKEYS)          // KSPLIT K-slabs
#define OFF_QSUM  (OFF_SC2  + KSPLIT*NROWS*CAND)
#define OFF_OUTM  (OFF_QSUM + NROWS*HID)
#define OFF_BFQ   (OFF_OUTM + NROWS*HID)
#define OFF_W2    (OFF_BFQ  + HID*HID)
#define OFF_B2    (OFF_W2   + HID*HID)
#define OFF_BF    (OFF_B2   + HID)
#define SCRATCH_F (OFF_BF   + HID)

__device__ float g_scratch[SCRATCH_F];
__device__ int   g_pairs[NCLS * CAP];
__device__ int   g_cnt[NCLS];
__device__ int   g_topc[NROWS * TOPK];   // per (row,slot): class * CPB

// ---------------------------------------------------------------------------
// SGEMM core v2: 64x64 tile, BK=32, 4x4/thread, reg prefetch.
// AM=0: A[M,K]; AM=1: A[K,M]. BM=0: B[K,N]; BM=1: B[N,K].
// ---------------------------------------------------------------------------
#define SROW 68

template <int AM, int BM>
__device__ __forceinline__ void gemm_tile2(
    const float* __restrict__ A, const float* __restrict__ B,
    const float* __restrict__ bias, float* __restrict__ C,
    int bm, int bn, int K, int lda, int ldb, int ldc, float* sbuf)
{
    float* As = sbuf;
    float* Bs = sbuf + 32 * SROW;
    const int tid = threadIdx.x;
    const int tx = tid & 15, ty = tid >> 4;

    float4 ra0, ra1, rb0, rb1;

    auto ldA = [&](int k0) {
        if constexpr (AM == 0) {
            int r = tid >> 3, c = (tid & 7) * 4;
            ra0 = *(const float4*)(A + (size_t)(bm + r)      * lda + k0 + c);
            ra1 = *(const float4*)(A + (size_t)(bm + r + 32) * lda + k0 + c);
        } else {
            int k = tid >> 4, c = (tid & 15) * 4;
            ra0 = *(const float4*)(A + (size_t)(k0 + k)      * lda + bm + c);
            ra1 = *(const float4*)(A + (size_t)(k0 + k + 16) * lda + bm + c);
        }
    };
    auto stA = [&]() {
        if constexpr (AM == 0) {
            int r = tid >> 3, c = (tid & 7) * 4;
            As[(c+0)*SROW + r] = ra0.x; As[(c+1)*SROW + r] = ra0.y;
            As[(c+2)*SROW + r] = ra0.z; As[(c+3)*SROW + r] = ra0.w;
            As[(c+0)*SROW + r+32] = ra1.x; As[(c+1)*SROW + r+32] = ra1.y;
            As[(c+2)*SROW + r+32] = ra1.z; As[(c+3)*SROW + r+32] = ra1.w;
        } else {
            int k = tid >> 4, c = (tid & 15) * 4;
            *(float4*)(As + k*SROW + c)      = ra0;
            *(float4*)(As + (k+16)*SROW + c) = ra1;
        }
    };
    auto ldB = [&](int k0) {
        if constexpr (BM == 1) {
            int r = tid >> 3, c = (tid & 7) * 4;
            rb0 = *(const float4*)(B + (size_t)(bn + r)      * ldb + k0 + c);
            rb1 = *(const float4*)(B + (size_t)(bn + r + 32) * ldb + k0 + c);
        } else {
            int k = tid >> 4, c = (tid & 15) * 4;
            rb0 = *(const float4*)(B + (size_t)(k0 + k)      * ldb + bn + c);
            rb1 = *(const float4*)(B + (size_t)(k0 + k + 16) * ldb + bn + c);
        }
    };
    auto stB = [&]() {
        if constexpr (BM == 1) {
            int r = tid >> 3, c = (tid & 7) * 4;
            Bs[(c+0)*SROW + r] = rb0.x; Bs[(c+1)*SROW + r] = rb0.y;
            Bs[(c+2)*SROW + r] = rb0.z; Bs[(c+3)*SROW + r] = rb0.w;
            Bs[(c+0)*SROW + r+32] = rb1.x; Bs[(c+1)*SROW + r+32] = rb1.y;
            Bs[(c+2)*SROW + r+32] = rb1.z; Bs[(c+3)*SROW + r+32] = rb1.w;
        } else {
            int k = tid >> 4, c = (tid & 15) * 4;
            *(float4*)(Bs + k*SROW + c)      = rb0;
            *(float4*)(Bs + (k+16)*SROW + c) = rb1;
        }
    };

    float acc[4][4] = {};
    ldA(0); ldB(0);
    for (int k0 = 0; k0 < K; k0 += 32) {
        stA(); stB();
        __syncthreads();
        if (k0 + 32 < K) { ldA(k0 + 32); ldB(k0 + 32); }
#pragma unroll
        for (int kk = 0; kk < 32; kk++) {
            float4 a = *(float4*)(As + kk*SROW + ty*4);
            float4 b = *(float4*)(Bs + kk*SROW + tx*4);
            acc[0][0] = fmaf(a.x, b.x, acc[0][0]); acc[0][1] = fmaf(a.x, b.y, acc[0][1]);
            acc[0][2] = fmaf(a.x, b.z, acc[0][2]); acc[0][3] = fmaf(a.x, b.w, acc[0][3]);
            acc[1][0] = fmaf(a.y, b.x, acc[1][0]); acc[1][1] = fmaf(a.y, b.y, acc[1][1]);
            acc[1][2] = fmaf(a.y, b.z, acc[1][2]); acc[1][3] = fmaf(a.y, b.w, acc[1][3]);
            acc[2][0] = fmaf(a.z, b.x, acc[2][0]); acc[2][1] = fmaf(a.z, b.y, acc[2][1]);
            acc[2][2] = fmaf(a.z, b.z, acc[2][2]); acc[2][3] = fmaf(a.z, b.w, acc[2][3]);
            acc[3][0] = fmaf(a.w, b.x, acc[3][0]); acc[3][1] = fmaf(a.w, b.y, acc[3][1]);
            acc[3][2] = fmaf(a.w, b.z, acc[3][2]); acc[3][3] = fmaf(a.w, b.w, acc[3][3]);
        }
        __syncthreads();
    }

    float4 bb = make_float4(0.f, 0.f, 0.f, 0.f);
    if (bias) bb = *(const float4*)(bias + bn + tx * 4);
#pragma unroll
    for (int i = 0; i < 4; i++) {
        int m = bm + ty * 4 + i;
        float4 v;
        v.x = acc[i][0] + bb.x; v.y = acc[i][1] + bb.y;
        v.z = acc[i][2] + bb.z; v.w = acc[i][3] + bb.w;
        *(float4*)(C + (size_t)m * ldc + bn + tx * 4) = v;
    }
}

// ---------------------------------------------------------------------------
// SGEMM core v3: 128x64 tile, BK=32, 8x4/thread.
// ---------------------------------------------------------------------------
#define AR3 132
#define BR3 68

template <int BM>
__device__ __forceinline__ void gemm_tile3(
    const float* __restrict__ A, const float* __restrict__ B,
    const float* __restrict__ bias, float* __restrict__ C,
    int bm, int bn, int K, int lda, int ldb, int ldc, float* sbuf)
{
    float* As = sbuf;             // [32][AR3]
    float* Bs = sbuf + 32 * AR3;  // [32][BR3]
    const int tid = threadIdx.x;
    const int tx = tid & 15, ty = tid >> 4;
    const int m0 = ty * 8, n0 = tx * 4;

    float4 ra[4], rb[2];
    auto ldA = [&](int k0) {
#pragma unroll
        for (int p = 0; p < 4; p++) {
            int idx = tid + p * 256;
            int r = idx >> 3, c4 = (idx & 7) * 4;
            ra[p] = *(const float4*)(A + (size_t)(bm + r) * lda + k0 + c4);
        }
    };
    auto stA = [&]() {
#pragma unroll
        for (int p = 0; p < 4; p++) {
            int idx = tid + p * 256;
            int r = idx >> 3, c4 = (idx & 7) * 4;
            As[(c4+0)*AR3 + r] = ra[p].x; As[(c4+1)*AR3 + r] = ra[p].y;
            As[(c4+2)*AR3 + r] = ra[p].z; As[(c4+3)*AR3 + r] = ra[p].w;
        }
    };
    auto ldB = [&](int k0) {
        if constexpr (BM == 1) {
#pragma unroll
            for (int p = 0; p < 2; p++) {
                int idx = tid + p * 256;
                int r = idx >> 3, c4 = (idx & 7) * 4;
                rb[p] = *(const float4*)(B + (size_t)(bn + r) * ldb + k0 + c4);
            }
        } else {
#pragma unroll
            for (int p = 0; p < 2; p++) {
                int idx = tid + p * 256;
                int k = idx >> 4, c4 = (idx & 15) * 4;
                rb[p] = *(const float4*)(B + (size_t)(k0 + k) * ldb + bn + c4);
            }
        }
    };
    auto stB = [&]() {
        if constexpr (BM == 1) {
#pragma unroll
            for (int p = 0; p < 2; p++) {
                int idx = tid + p * 256;
                int r = idx >> 3, c4 = (idx & 7) * 4;
                Bs[(c4+0)*BR3 + r] = rb[p].x; Bs[(c4+1)*BR3 + r] = rb[p].y;
                Bs[(c4+2)*BR3 + r] = rb[p].z; Bs[(c4+3)*BR3 + r] = rb[p].w;
            }
        } else {
#pragma unroll
            for (int p = 0; p < 2; p++) {
                int idx = tid + p * 256;
                int k = idx >> 4, c4 = (idx & 15) * 4;
                *(float4*)(Bs + k*BR3 + c4) = rb[p];
            }
        }
    };

    float acc[8][4] = {};
    ldA(0); ldB(0);
    for (int k0 = 0; k0 < K; k0 += 32) {
        stA(); stB();
        __syncthreads();
        if (k0 + 32 < K) { ldA(k0 + 32); ldB(k0 + 32); }
#pragma unroll
        for (int kk = 0; kk < 32; kk++) {
            float4 a0 = *(float4*)(As + kk*AR3 + m0);
            float4 a1 = *(float4*)(As + kk*AR3 + m0 + 4);
            float4 b  = *(float4*)(Bs + kk*BR3 + n0);
            acc[0][0] = fmaf(a0.x,b.x,acc[0][0]); acc[0][1] = fmaf(a0.x,b.y,acc[0][1]);
            acc[0][2] = fmaf(a0.x,b.z,acc[0][2]); acc[0][3] = fmaf(a0.x,b.w,acc[0][3]);
            acc[1][0] = fmaf(a0.y,b.x,acc[1][0]); acc[1][1] = fmaf(a0.y,b.y,acc[1][1]);
            acc[1][2] = fmaf(a0.y,b.z,acc[1][2]); acc[1][3] = fmaf(a0.y,b.w,acc[1][3]);
            acc[2][0] = fmaf(a0.z,b.x,acc[2][0]); acc[2][1] = fmaf(a0.z,b.y,acc[2][1]);
            acc[2][2] = fmaf(a0.z,b.z,acc[2][2]); acc[2][3] = fmaf(a0.z,b.w,acc[2][3]);
            acc[3][0] = fmaf(a0.w,b.x,acc[3][0]); acc[3][1] = fmaf(a0.w,b.y,acc[3][1]);
            acc[3][2] = fmaf(a0.w,b.z,acc[3][2]); acc[3][3] = fmaf(a0.w,b.w,acc[3][3]);
            acc[4][0] = fmaf(a1.x,b.x,acc[4][0]); acc[4][1] = fmaf(a1.x,b.y,acc[4][1]);
            acc[4][2] = fmaf(a1.x,b.z,acc[4][2]); acc[4][3] = fmaf(a1.x,b.w,acc[4][3]);
            acc[5][0] = fmaf(a1.y,b.x,acc[5][0]); acc[5][1] = fmaf(a1.y,b.y,acc[5][1]);
            acc[5][2] = fmaf(a1.y,b.z,acc[5][2]); acc[5][3] = fmaf(a1.y,b.w,acc[5][3]);
            acc[6][0] = fmaf(a1.z,b.x,acc[6][0]); acc[6][1] = fmaf(a1.z,b.y,acc[6][1]);
            acc[6][2] = fmaf(a1.z,b.z,acc[6][2]); acc[6][3] = fmaf(a1.z,b.w,acc[6][3]);
            acc[7][0] = fmaf(a1.w,b.x,acc[7][0]); acc[7][1] = fmaf(a1.w,b.y,acc[7][1]);
            acc[7][2] = fmaf(a1.w,b.z,acc[7][2]); acc[7][3] = fmaf(a1.w,b.w,acc[7][3]);
        }
        __syncthreads();
    }

    float4 bb = make_float4(0.f, 0.f, 0.f, 0.f);
    if (bias) bb = *(const float4*)(bias + bn + n0);
#pragma unroll
    for (int i = 0; i < 8; i++) {
        int m = bm + m0 + i;
        float4 v;
        v.x = acc[i][0] + bb.x; v.y = acc[i][1] + bb.y;
        v.z = acc[i][2] + bb.z; v.w = acc[i][3] + bb.w;
        *(float4*)(C + (size_t)m * ldc + bn + n0) = v;
    }
}

#define SBUF3 (32 * AR3 + 32 * BR3)

// ---------------------------------------------------------------------------
// K1: KEY (tile2, 60), QRY (tile3, 32), W2 (tile2<1,0>, 16), BFQ (tile2, 16),
// bias/B2/cnt (1). grid 125. W2 = qq_w^T @ kq_w; B2 = qq_b @ kq_w.
// ---------------------------------------------------------------------------
__global__ __launch_bounds__(256)
void k1_proj(const float* __restrict__ memkey, const float* __restrict__ h,
             const float* __restrict__ key_w,  const float* __restrict__ key_b,
             const float* __restrict__ query_w,const float* __restrict__ query_b,
             const float* __restrict__ qq_w,   const float* __restrict__ qq_b,
             const float* __restrict__ kq_w,   const float* __restrict__ kq_b,
             const float* __restrict__ proto_w,const float* __restrict__ proto_b,
             float* __restrict__ KEY, float* __restrict__ QRY, float* __restrict__ W2,
             float* __restrict__ BFQ, float* __restrict__ B2, float* __restrict__ BF)
{
    __shared__ __align__(16) float sbuf[SBUF3];
    const int b = blockIdx.x;
    if (b < 60) {
        gemm_tile2<0,1>(memkey, key_w, key_b, KEY, (b/4)*64, (b%4)*64, HID, HID, HID, HID, sbuf);
    } else if (b < 92) {
        int i = b - 60;
        gemm_tile3<1>(h, query_w, query_b, QRY, (i/4)*128, (i%4)*64, HID, HID, HID, HID, sbuf);
    } else if (b < 108) {
        int i = b - 92;   // W2[i][j] = sum_o qq_w[o][i] * kq_w[o][j]
        gemm_tile2<1,0>(qq_w, kq_w, nullptr, W2, (i/4)*64, (i%4)*64, HID, HID, HID, HID, sbuf);
    } else if (b < 124) {
        int i = b - 108;
        gemm_tile2<1,1>(kq_w, proto_w, nullptr, BFQ, (i/4)*64, (i%4)*64, HID, HID, 2*HID, HID, sbuf);
    } else {
        const int t = threadIdx.x;
        float s1 = 0.f;
        for (int o = 0; o < HID; o++)
            s1 = fmaf(qq_b[o], kq_w[(size_t)o * HID + t], s1);
        B2[t] = s1;
        float s2 = proto_b[t];
        for (int c = 0; c < HID; c++)
            s2 = fmaf(kq_b[c], proto_w[(size_t)t * (2*HID) + c], s2);
        BF[t] = s2;
        if (t < NCLS) g_cnt[t] = 0;
    }
}

// ---------------------------------------------------------------------------
// K2: SC1 (tile3, 120), QHAT = h@W2+B2 (tile3 BM=0, 32), KEYP (tile2, 60).
// grid 212.
// ---------------------------------------------------------------------------
__global__ __launch_bounds__(256)
void k2_score1(const float* __restrict__ QRY, const float* __restrict__ KEY,
               const float* __restrict__ h,   const float* __restrict__ W2,
               const float* __restrict__ B2,  const float* __restrict__ proto_w,
               float* __restrict__ SC1, float* __restrict__ QHAT, float* __restrict__ KEYP)
{
    __shared__ __align__(16) float sbuf[SBUF3];
    const int b = blockIdx.x;
    if (b < 120) {
        gemm_tile3<1>(QRY, KEY, nullptr, SC1, (b/15)*128, (b%15)*64, HID, HID, HID, NKEYS, sbuf);
    } else if (b < 152) {
        int i = b - 120;
        gemm_tile3<0>(h, W2, B2, QHAT, (i/4)*128, (i%4)*64, HID, HID, HID, HID, sbuf);
    } else {
        int i = b - 152;
        gemm_tile2<0,1>(KEY, proto_w + HID, nullptr, KEYP, (i/4)*64, (i%4)*64, HID, HID, 2*HID, HID, sbuf);
    }
}

// ---------------------------------------------------------------------------
// K3: warp-per-row top-5 of 960 via register lists + shfl symmetric merges.
// Records g_topc for k56.
// ---------------------------------------------------------------------------
__global__ __launch_bounds__(256)
void k3_topk1(const float* __restrict__ SC1, const float* __restrict__ KEYP,
              float* __restrict__ OUTM)
{
    const int lane = threadIdx.x & 31;
    const int n = blockIdx.x * 8 + (threadIdx.x >> 5);

    float lv[TOPK]; int li[TOPK];
#pragma unroll
    for (int j = 0; j < TOPK; j++) { lv[j] = -INFINITY; li[j] = 0x7fffffff; }

    const float* row = SC1 + (size_t)n * NKEYS;
#pragma unroll 6
    for (int i = 0; i < NKEYS / 32; i++) {
        int idx = i * 32 + lane;
        float v = row[idx];
        if (v > lv[TOPK-1]) {
            int p = TOPK - 1;
            while (p > 0 && v > lv[p-1]) { lv[p] = lv[p-1]; li[p] = li[p-1]; p--; }
            lv[p] = v; li[p] = idx;
        }
    }

#pragma unroll
    for (int off = 16; off >= 1; off >>= 1) {
        float pv[TOPK]; int pi[TOPK];
#pragma unroll
        for (int j = 0; j < TOPK; j++) {
            pv[j] = __shfl_xor_sync(0xffffffffu, lv[j], off);
            pi[j] = __shfl_xor_sync(0xffffffffu, li[j], off);
        }
        float ov[TOPK]; int oi[TOPK];
        int pa = 0, pb = 0;
#pragma unroll
        for (int j = 0; j < TOPK; j++) {
            bool ta = (lv[pa] > pv[pb]) || (lv[pa] == pv[pb] && li[pa] < pi[pb]);
            if (ta) { ov[j] = lv[pa]; oi[j] = li[pa]; pa++; }
            else    { ov[j] = pv[pb]; oi[j] = pi[pb]; pb++; }
        }
#pragma unroll
        for (int j = 0; j < TOPK; j++) { lv[j] = ov[j]; li[j] = oi[j]; }
    }

    float w[TOPK];
    float mx = lv[0], den = 0.f;
#pragma unroll
    for (int j = 0; j < TOPK; j++) { w[j] = expf(lv[j] - mx); den += w[j]; }
    float dinv = 1.f / den;
#pragma unroll
    for (int j = 0; j < TOPK; j++) w[j] *= dinv;

    if (lane == 0) {
#pragma unroll
        for (int j = 0; j < TOPK; j++) {
            int c = li[j] / DCS;
            g_topc[n * TOPK + j] = c * CPB;
            int p = atomicAdd(&g_cnt[c], 1);
            g_pairs[c * CAP + p] = n * 8 + j;
        }
    }

#pragma unroll
    for (int i = 0; i < HID / 32; i++) {
        int d = i * 32 + lane;
        float acc = 0.f;
#pragma unroll
        for (int j = 0; j < TOPK; j++)
            acc = fmaf(w[j], KEYP[(size_t)li[j] * HID + d], acc);
        OUTM[(size_t)n * HID + d] = acc;
    }
}

// ---------------------------------------------------------------------------
// K4: class-batched scoring GEMM, split-K(4), B resident in smem.
// grid (60, 12).
// ---------------------------------------------------------------------------
__global__ __launch_bounds__(256)
void k4_score2(const float* __restrict__ QHAT, const float* __restrict__ rawq,
               float* __restrict__ SC2)
{
    __shared__ float Bsh[64][85];
    __shared__ __align__(16) float As[32][68];
    __shared__ int   spn[64], spj[64];

    const int c = blockIdx.x, tid = threadIdx.x;
    const int kh = blockIdx.y & 3;
    const int ty0 = blockIdx.y >> 2;
    const int kbase = kh * 64;
    const int cnt = g_cnt[c];
    const int tm = tid >> 4, tn = tid & 15;
    const float* rbase = rawq + (size_t)c * CPB * HID;
    float* outb = SC2 + (size_t)kh * NROWS * CAND;

#pragma unroll
    for (int p = 0; p < 5; p++) {
        int idx = tid + p * 256;
        int q = idx >> 4, c4 = (idx & 15) * 4;
        float4 v = *(const float4*)(rbase + (size_t)q * HID + kbase + c4);
        Bsh[c4+0][q] = v.x; Bsh[c4+1][q] = v.y;
        Bsh[c4+2][q] = v.z; Bsh[c4+3][q] = v.w;
    }

    const int am0 = tid >> 3, ac0 = (tid & 7) * 4;
    const int am1 = (tid + 256) >> 3, ac1 = ((tid + 256) & 7) * 4;
    float4 rA0, rA1;

    for (int tt = ty0; tt * 64 < cnt; tt += 3) {
        const int m0 = tt * 64;
        __syncthreads();
        if (tid < 64) {
            int mi = m0 + tid;
            int pm = g_pairs[c * CAP + (mi < cnt ? mi : m0)];
            spn[tid] = pm >> 3; spj[tid] = pm & 7;
        }
        __syncthreads();

        auto ldA = [&](int k0) {
            rA0 = *(const float4*)(QHAT + (size_t)spn[am0] * HID + k0 + ac0);
            rA1 = *(const float4*)(QHAT + (size_t)spn[am1] * HID + k0 + ac1);
        };
        auto stA = [&]() {
            As[ac0+0][am0] = rA0.x; As[ac0+1][am0] = rA0.y;
            As[ac0+2][am0] = rA0.z; As[ac0+3][am0] = rA0.w;
            As[ac1+0][am1] = rA1.x; As[ac1+1][am1] = rA1.y;
            As[ac1+2][am1] = rA1.z; As[ac1+3][am1] = rA1.w;
        };

        float acc[4][5] = {};
        ldA(kbase);
        for (int kc = 0; kc < 2; kc++) {
            stA();
            __syncthreads();
            if (kc < 1) ldA(kbase + 32);
            const int kb = kc * 32;
#pragma unroll
            for (int kk = 0; kk < 32; kk++) {
                float4 a = *(float4*)&As[kk][tm * 4];
                float b0 = Bsh[kb+kk][tn*5+0], b1 = Bsh[kb+kk][tn*5+1], b2 = Bsh[kb+kk][tn*5+2];
                float b3 = Bsh[kb+kk][tn*5+3], b4 = Bsh[kb+kk][tn*5+4];
                acc[0][0] = fmaf(a.x,b0,acc[0][0]); acc[0][1] = fmaf(a.x,b1,acc[0][1]);
                acc[0][2] = fmaf(a.x,b2,acc[0][2]); acc[0][3] = fmaf(a.x,b3,acc[0][3]);
                acc[0][4] = fmaf(a.x,b4,acc[0][4]);
                acc[1][0] = fmaf(a.y,b0,acc[1][0]); acc[1][1] = fmaf(a.y,b1,acc[1][1]);
                acc[1][2] = fmaf(a.y,b2,acc[1][2]); acc[1][3] = fmaf(a.y,b3,acc[1][3]);
                acc[1][4] = fmaf(a.y,b4,acc[1][4]);
                acc[2][0] = fmaf(a.z,b0,acc[2][0]); acc[2][1] = fmaf(a.z,b1,acc[2][1]);
                acc[2][2] = fmaf(a.z,b2,acc[2][2]); acc[2][3] = fmaf(a.z,b3,acc[2][3]);
                acc[2][4] = fmaf(a.z,b4,acc[2][4]);
                acc[3][0] = fmaf(a.w,b0,acc[3][0]); acc[3][1] = fmaf(a.w,b1,acc[3][1]);
                acc[3][2] = fmaf(a.w,b2,acc[3][2]); acc[3][3] = fmaf(a.w,b3,acc[3][3]);
                acc[3][4] = fmaf(a.w,b4,acc[3][4]);
            }
            __syncthreads();
        }
#pragma unroll
        for (int i = 0; i < 4; i++) {
            int m = tm * 4 + i;
            if (m0 + m < cnt) {
                float* dst = outb + (size_t)spn[m] * CAND + spj[m] * CPB + tn * 5;
#pragma unroll
                for (int jq = 0; jq < 5; jq++) dst[jq] = acc[i][jq];
            }
        }
    }
}

// ---------------------------------------------------------------------------
// K56: fused per-row select + weighted gather-sum (R12 version, unchanged).
// ---------------------------------------------------------------------------
__global__ __launch_bounds__(256)
void k56_select_wsum(const float* __restrict__ SC2, const float* __restrict__ rawq,
                     float* __restrict__ QSUM)
{
    __shared__ float sc[CAND];
    __shared__ float sb[512];
    __shared__ float rr[256];
    __shared__ int   ii[256];
    __shared__ int   ta[512], tb[512];
    __shared__ int   selrow[TOPKQ];
    __shared__ float selw[TOPKQ];
    __shared__ int   cls[TOPK];
    __shared__ float s_den;
    __shared__ int   s_G;

    const int n = blockIdx.x, tid = threadIdx.x;

    if (tid < TOPK) cls[tid] = g_topc[n * TOPK + tid];
    {
        float v0 = 0.f, v1 = 0.f;
#pragma unroll
        for (int s = 0; s < KSPLIT; s++) {
            const float* slab = SC2 + (size_t)s * NROWS * CAND + (size_t)n * CAND;
            v0 += slab[tid];
            if (tid < CAND - 256) v1 += slab[tid + 256];
        }
        sc[tid] = v0;
        if (tid < CAND - 256) sc[tid + 256] = v1;
    }
    __syncthreads();

    sb[tid] = sc[tid];
    sb[tid + 256] = (tid < CAND - 256) ? sc[tid + 256] : -INFINITY;
    __syncthreads();
    for (int k = 2; k <= 512; k <<= 1) {
        for (int j = k >> 1; j > 0; j >>= 1) {
#pragma unroll
            for (int t = 0; t < 2; t++) {
                int i = tid + t * 256;
                int ixj = i ^ j;
                if (ixj > i) {
                    float a = sb[i], b = sb[ixj];
                    if ((a > b) == ((i & k) == 0)) { sb[i] = b; sb[ixj] = a; }
                }
            }
            __syncthreads();
        }
    }
    const float T  = sb[512 - TOPKQ];
    const float mx = sb[511];

    {
        int cnt = 0; float den = 0.f;
        float v = sc[tid];
        if (v > T) { cnt++; den += expf(v - mx); }
        if (tid < CAND - 256) {
            float v2 = sc[tid + 256];
            if (v2 > T) { cnt++; den += expf(v2 - mx); }
        }
        rr[tid] = den; ii[tid] = cnt;
    }
    __syncthreads();
    for (int off = 128; off > 0; off >>= 1) {
        if (tid < off) { rr[tid] += rr[tid + off]; ii[tid] += ii[tid + off]; }
        __syncthreads();
    }
    if (tid == 0) {
        s_G = ii[0];
        s_den = rr[0] + (float)(TOPKQ - ii[0]) * expf(T - mx);
    }
    __syncthreads();
    const int   G = s_G;
    const float dinv = 1.f / s_den;

    ta[tid]       = (sc[tid] > T) ? 1 : 0;
    ta[tid + 256] = (tid < CAND - 256 && sc[tid + 256] > T) ? 1 : 0;
    __syncthreads();
    {
        int* src = ta; int* dst = tb;
        for (int d = 1; d < 512; d <<= 1) {
            dst[tid]       = src[tid]       + (tid >= d ? src[tid - d] : 0);
            dst[tid + 256] = src[tid + 256] + (tid + 256 >= d ? src[tid + 256 - d] : 0);
            __syncthreads();
            int* t = src; src = dst; dst = t;
        }
#pragma unroll
        for (int t = 0; t < 2; t++) {
            int m = tid + t * 256;
            if (m < CAND && sc[m] > T) {
                int p = src[m] - 1;
                selrow[p] = cls[m / CPB] + (m % CPB);
                selw[p]   = expf(sc[m] - mx) * dinv;
            }
        }
    }
    __syncthreads();

    ta[tid]       = (sc[tid] == T) ? 1 : 0;
    ta[tid + 256] = (tid < CAND - 256 && sc[tid + 256] == T) ? 1 : 0;
    __syncthreads();
    {
        int* src = ta; int* dst = tb;
        for (int d = 1; d < 512; d <<= 1) {
            dst[tid]       = src[tid]       + (tid >= d ? src[tid - d] : 0);
            dst[tid + 256] = src[tid + 256] + (tid + 256 >= d ? src[tid + 256 - d] : 0);
            __syncthreads();
            int* t = src; src = dst; dst = t;
        }
        const float wT = expf(T - mx) * dinv;
#pragma unroll
        for (int t = 0; t < 2; t++) {
            int m = tid + t * 256;
            if (m < CAND && sc[m] == T) {
                int r = src[m] - 1;
                if (r < TOPKQ - G) {
                    selrow[G + r] = cls[m / CPB] + (m % CPB);
                    selw[G + r]   = wT;
                }
            }
        }
    }
    __syncthreads();

    float acc0 = 0.f, acc1 = 0.f, acc2 = 0.f, acc3 = 0.f;
    for (int p = 0; p < TOPKQ; p += 4) {
        acc0 = fmaf(selw[p + 0], rawq[(size_t)selrow[p + 0] * HID + tid], acc0);
        acc1 = fmaf(selw[p + 1], rawq[(size_t)selrow[p + 1] * HID + tid], acc1);
        acc2 = fmaf(selw[p + 2], rawq[(size_t)selrow[p + 2] * HID + tid], acc2);
        acc3 = fmaf(selw[p + 3], rawq[(size_t)selrow[p + 3] * HID + tid], acc3);
    }
    QSUM[(size_t)n * HID + tid] = (acc0 + acc1) + (acc2 + acc3);
}

// ---------------------------------------------------------------------------
// K7: out = QSUM @ BfQ + OUTM + bf.  tile 64m x 32n, grid (8, 16)
// ---------------------------------------------------------------------------
__global__ __launch_bounds__(256)
void k7_out(const float* __restrict__ QSUM, const float* __restrict__ BFQ,
            const float* __restrict__ OUTM, const float* __restrict__ BF,
            float* __restrict__ out)
{
    __shared__ float As[32][65];
    __shared__ float Bsh[32][36];
    const int tid = threadIdx.x;
    const int bm = blockIdx.y * 64, bn = blockIdx.x * 32;
    const int ty = tid >> 3, tx = tid & 7;

    float acc[2][4] = {};
    for (int k0 = 0; k0 < HID; k0 += 32) {
        __syncthreads();
        {
            int r = tid >> 3, c4 = (tid & 7) * 4;
#pragma unroll
            for (int h = 0; h < 2; h++) {
                int m = bm + r + h * 32;
                float4 v = *(const float4*)(QSUM + (size_t)m * HID + k0 + c4);
                As[c4+0][r + h*32] = v.x; As[c4+1][r + h*32] = v.y;
                As[c4+2][r + h*32] = v.z; As[c4+3][r + h*32] = v.w;
            }
        }
        {
            int k = tid >> 3, c4 = (tid & 7) * 4;
            *(float4*)&Bsh[k][c4] = *(const float4*)(BFQ + (size_t)(k0 + k) * HID + bn + c4);
        }
        __syncthreads();
#pragma unroll
        for (int kk = 0; kk < 32; kk++) {
            float a0 = As[kk][ty*2 + 0], a1 = As[kk][ty*2 + 1];
            float4 b = *(float4*)&Bsh[kk][tx*4];
            acc[0][0] = fmaf(a0,b.x,acc[0][0]); acc[0][1] = fmaf(a0,b.y,acc[0][1]);
            acc[0][2] = fmaf(a0,b.z,acc[0][2]); acc[0][3] = fmaf(a0,b.w,acc[0][3]);
            acc[1][0] = fmaf(a1,b.x,acc[1][0]); acc[1][1] = fmaf(a1,b.y,acc[1][1]);
            acc[1][2] = fmaf(a1,b.z,acc[1][2]); acc[1][3] = fmaf(a1,b.w,acc[1][3]);
        }
    }

    float4 bb = *(const float4*)(BF + bn + tx * 4);
#pragma unroll
    for (int i = 0; i < 2; i++) {
        int m = bm + ty * 2 + i;
        float4 om = *(const float4*)(OUTM + (size_t)m * HID + bn + tx * 4);
        float4 v;
        v.x = acc[i][0] + bb.x + om.x; v.y = acc[i][1] + bb.y + om.y;
        v.z = acc[i][2] + bb.z + om.z; v.w = acc[i][3] + bb.w + om.w;
        *(float4*)(out + (size_t)m * HID + bn + tx * 4) = v;
    }
}

// ---------------------------------------------------------------------------
extern "C" void kernel_launch(void* const* d_in, const int* in_sizes, int n_in,
                              void* d_out, int out_size)
{
    const int sh = (n_in >= 15) ? 0 : 1;
    const float* h          = (const float*)d_in[0];
    const float* memory_key = (const float*)d_in[3 - sh];
    const float* queue_key  = (const float*)d_in[4 - sh];
    const float* key_w      = (const float*)d_in[5 - sh];
    const float* key_b      = (const float*)d_in[6 - sh];
    const float* query_w    = (const float*)d_in[7 - sh];
    const float* query_b    = (const float*)d_in[8 - sh];
    const float* kq_w       = (const float*)d_in[9 - sh];
    const float* kq_b       = (const float*)d_in[10 - sh];
    const float* qq_w       = (const float*)d_in[11 - sh];
    const float* qq_b       = (const float*)d_in[12 - sh];
    const float* proto_w    = (const float*)d_in[13 - sh];
    const float* proto_b    = (const float*)d_in[14 - sh];
    float* out = (float*)d_out;

    void* sp = nullptr; cudaGetSymbolAddress(&sp, g_scratch);
    float* S = (float*)sp;
    float* KEY  = S + OFF_KEY;
    float* QRY  = S + OFF_QRY;
    float* QHAT = S + OFF_QHAT;
    float* KEYP = S + OFF_KEYP;
    float* SC1  = S + OFF_SC1;
    float* SC2  = S + OFF_SC2;
    float* QSUM = S + OFF_QSUM;
    float* OUTM = S + OFF_OUTM;
    float* BFQ  = S + OFF_BFQ;
    float* W2   = S + OFF_W2;
    float* B2   = S + OFF_B2;
    float* BF   = S + OFF_BF;

    k1_proj<<<125, 256>>>(memory_key, h, key_w, key_b, query_w, query_b,
                          qq_w, qq_b, kq_w, kq_b, proto_w, proto_b,
                          KEY, QRY, W2, BFQ, B2, BF);
    k2_score1<<<212, 256>>>(QRY, KEY, h, W2, B2, proto_w, SC1, QHAT, KEYP);
    k3_topk1<<<NROWS / 8, 256>>>(SC1, KEYP, OUTM);
    k4_score2<<<dim3(60, 12), 256>>>(QHAT, queue_key, SC2);
    k56_select_wsum<<<NROWS, 256>>>(SC2, queue_key, QSUM);
    k7_out<<<dim3(8, 16), 256>>>(QSUM, BFQ, OUTM, BF, out);
}

// round 14
// speedup vs baseline: 1.0281x; 1.0281x over previous
#include <cuda_runtime.h>
#include <math.h>

#define HID    256
#define BS     64
#define DCS    16
#define NCLS   60
#define QSZ    5
#define TOPK   5
#define TOPKQ  100
#define NROWS  (BS * DCS)          // 1024
#define NKEYS  (NCLS * DCS)        // 960
#define CAND   (TOPK * QSZ * DCS)  // 400
#define CPB    (QSZ * DCS)         // 80
#define CAP    (NROWS * TOPK)      // 5120 max pairs per class
#define KSPLIT 8

// ---------------------------------------------------------------------------
// Scratch (float):
#define OFF_KEY   0
#define OFF_QRY   (OFF_KEY  + NKEYS*HID)
#define OFF_QQ    (OFF_QRY  + NROWS*HID)
#define OFF_QHAT  (OFF_QQ   + NROWS*HID)
#define OFF_KEYP  (OFF_QHAT + NROWS*HID)
#define OFF_SC1   (OFF_KEYP + NKEYS*HID)
#define OFF_SC2   (OFF_SC1  + NROWS*NKEYS)          // KSPLIT K-slabs
#define OFF_QSUM  (OFF_SC2  + KSPLIT*NROWS*CAND)
#define OFF_OUTM  (OFF_QSUM + NROWS*HID)
#define OFF_BFQ   (OFF_OUTM + NROWS*HID)
#define OFF_BF    (OFF_BFQ  + HID*HID)
#define SCRATCH_F (OFF_BF   + HID)

__device__ float g_scratch[SCRATCH_F];
__device__ int   g_pairs[NCLS * CAP];
__device__ int   g_cnt[NCLS];
__device__ int   g_topc[NROWS * TOPK];   // per (row,slot): class * CPB

// ---------------------------------------------------------------------------
// SGEMM core v2: 64x64 tile, BK=32, 4x4/thread, reg prefetch.
// AM=0: A[M,K]; AM=1: A[K,M]. BM=0: B[K,N]; BM=1: B[N,K].
// ---------------------------------------------------------------------------
#define SROW 68

template <int AM, int BM>
__device__ __forceinline__ void gemm_tile2(
    const float* __restrict__ A, const float* __restrict__ B,
    const float* __restrict__ bias, float* __restrict__ C,
    int bm, int bn, int K, int lda, int ldb, int ldc, float* sbuf)
{
    float* As = sbuf;
    float* Bs = sbuf + 32 * SROW;
    const int tid = threadIdx.x;
    const int tx = tid & 15, ty = tid >> 4;

    float4 ra0, ra1, rb0, rb1;

    auto ldA = [&](int k0) {
        if constexpr (AM == 0) {
            int r = tid >> 3, c = (tid & 7) * 4;
            ra0 = *(const float4*)(A + (size_t)(bm + r)      * lda + k0 + c);
            ra1 = *(const float4*)(A + (size_t)(bm + r + 32) * lda + k0 + c);
        } else {
            int k = tid >> 4, c = (tid & 15) * 4;
            ra0 = *(const float4*)(A + (size_t)(k0 + k)      * lda + bm + c);
            ra1 = *(const float4*)(A + (size_t)(k0 + k + 16) * lda + bm + c);
        }
    };
    auto stA = [&]() {
        if constexpr (AM == 0) {
            int r = tid >> 3, c = (tid & 7) * 4;
            As[(c+0)*SROW + r] = ra0.x; As[(c+1)*SROW + r] = ra0.y;
            As[(c+2)*SROW + r] = ra0.z; As[(c+3)*SROW + r] = ra0.w;
            As[(c+0)*SROW + r+32] = ra1.x; As[(c+1)*SROW + r+32] = ra1.y;
            As[(c+2)*SROW + r+32] = ra1.z; As[(c+3)*SROW + r+32] = ra1.w;
        } else {
            int k = tid >> 4, c = (tid & 15) * 4;
            *(float4*)(As + k*SROW + c)      = ra0;
            *(float4*)(As + (k+16)*SROW + c) = ra1;
        }
    };
    auto ldB = [&](int k0) {
        if constexpr (BM == 1) {
            int r = tid >> 3, c = (tid & 7) * 4;
            rb0 = *(const float4*)(B + (size_t)(bn + r)      * ldb + k0 + c);
            rb1 = *(const float4*)(B + (size_t)(bn + r + 32) * ldb + k0 + c);
        } else {
            int k = tid >> 4, c = (tid & 15) * 4;
            rb0 = *(const float4*)(B + (size_t)(k0 + k)      * ldb + bn + c);
            rb1 = *(const float4*)(B + (size_t)(k0 + k + 16) * ldb + bn + c);
        }
    };
    auto stB = [&]() {
        if constexpr (BM == 1) {
            int r = tid >> 3, c = (tid & 7) * 4;
            Bs[(c+0)*SROW + r] = rb0.x; Bs[(c+1)*SROW + r] = rb0.y;
            Bs[(c+2)*SROW + r] = rb0.z; Bs[(c+3)*SROW + r] = rb0.w;
            Bs[(c+0)*SROW + r+32] = rb1.x; Bs[(c+1)*SROW + r+32] = rb1.y;
            Bs[(c+2)*SROW + r+32] = rb1.z; Bs[(c+3)*SROW + r+32] = rb1.w;
        } else {
            int k = tid >> 4, c = (tid & 15) * 4;
            *(float4*)(Bs + k*SROW + c)      = rb0;
            *(float4*)(Bs + (k+16)*SROW + c) = rb1;
        }
    };

    float acc[4][4] = {};
    ldA(0); ldB(0);
    for (int k0 = 0; k0 < K; k0 += 32) {
        stA(); stB();
        __syncthreads();
        if (k0 + 32 < K) { ldA(k0 + 32); ldB(k0 + 32); }
#pragma unroll
        for (int kk = 0; kk < 32; kk++) {
            float4 a = *(float4*)(As + kk*SROW + ty*4);
            float4 b = *(float4*)(Bs + kk*SROW + tx*4);
            acc[0][0] = fmaf(a.x, b.x, acc[0][0]); acc[0][1] = fmaf(a.x, b.y, acc[0][1]);
            acc[0][2] = fmaf(a.x, b.z, acc[0][2]); acc[0][3] = fmaf(a.x, b.w, acc[0][3]);
            acc[1][0] = fmaf(a.y, b.x, acc[1][0]); acc[1][1] = fmaf(a.y, b.y, acc[1][1]);
            acc[1][2] = fmaf(a.y, b.z, acc[1][2]); acc[1][3] = fmaf(a.y, b.w, acc[1][3]);
            acc[2][0] = fmaf(a.z, b.x, acc[2][0]); acc[2][1] = fmaf(a.z, b.y, acc[2][1]);
            acc[2][2] = fmaf(a.z, b.z, acc[2][2]); acc[2][3] = fmaf(a.z, b.w, acc[2][3]);
            acc[3][0] = fmaf(a.w, b.x, acc[3][0]); acc[3][1] = fmaf(a.w, b.y, acc[3][1]);
            acc[3][2] = fmaf(a.w, b.z, acc[3][2]); acc[3][3] = fmaf(a.w, b.w, acc[3][3]);
        }
        __syncthreads();
    }

    float4 bb = make_float4(0.f, 0.f, 0.f, 0.f);
    if (bias) bb = *(const float4*)(bias + bn + tx * 4);
#pragma unroll
    for (int i = 0; i < 4; i++) {
        int m = bm + ty * 4 + i;
        float4 v;
        v.x = acc[i][0] + bb.x; v.y = acc[i][1] + bb.y;
        v.z = acc[i][2] + bb.z; v.w = acc[i][3] + bb.w;
        *(float4*)(C + (size_t)m * ldc + bn + tx * 4) = v;
    }
}

// ---------------------------------------------------------------------------
// SGEMM core v3: 128x64 tile, BK=32, 8x4/thread.
// ---------------------------------------------------------------------------
#define AR3 132
#define BR3 68

template <int BM>
__device__ __forceinline__ void gemm_tile3(
    const float* __restrict__ A, const float* __restrict__ B,
    const float* __restrict__ bias, float* __restrict__ C,
    int bm, int bn, int K, int lda, int ldb, int ldc, float* sbuf)
{
    float* As = sbuf;             // [32][AR3]
    float* Bs = sbuf + 32 * AR3;  // [32][BR3]
    const int tid = threadIdx.x;
    const int tx = tid & 15, ty = tid >> 4;
    const int m0 = ty * 8, n0 = tx * 4;

    float4 ra[4], rb[2];
    auto ldA = [&](int k0) {
#pragma unroll
        for (int p = 0; p < 4; p++) {
            int idx = tid + p * 256;
            int r = idx >> 3, c4 = (idx & 7) * 4;
            ra[p] = *(const float4*)(A + (size_t)(bm + r) * lda + k0 + c4);
        }
    };
    auto stA = [&]() {
#pragma unroll
        for (int p = 0; p < 4; p++) {
            int idx = tid + p * 256;
            int r = idx >> 3, c4 = (idx & 7) * 4;
            As[(c4+0)*AR3 + r] = ra[p].x; As[(c4+1)*AR3 + r] = ra[p].y;
            As[(c4+2)*AR3 + r] = ra[p].z; As[(c4+3)*AR3 + r] = ra[p].w;
        }
    };
    auto ldB = [&](int k0) {
        if constexpr (BM == 1) {
#pragma unroll
            for (int p = 0; p < 2; p++) {
                int idx = tid + p * 256;
                int r = idx >> 3, c4 = (idx & 7) * 4;
                rb[p] = *(const float4*)(B + (size_t)(bn + r) * ldb + k0 + c4);
            }
        } else {
#pragma unroll
            for (int p = 0; p < 2; p++) {
                int idx = tid + p * 256;
                int k = idx >> 4, c4 = (idx & 15) * 4;
                rb[p] = *(const float4*)(B + (size_t)(k0 + k) * ldb + bn + c4);
            }
        }
    };
    auto stB = [&]() {
        if constexpr (BM == 1) {
#pragma unroll
            for (int p = 0; p < 2; p++) {
                int idx = tid + p * 256;
                int r = idx >> 3, c4 = (idx & 7) * 4;
                Bs[(c4+0)*BR3 + r] = rb[p].x; Bs[(c4+1)*BR3 + r] = rb[p].y;
                Bs[(c4+2)*BR3 + r] = rb[p].z; Bs[(c4+3)*BR3 + r] = rb[p].w;
            }
        } else {
#pragma unroll
            for (int p = 0; p < 2; p++) {
                int idx = tid + p * 256;
                int k = idx >> 4, c4 = (idx & 15) * 4;
                *(float4*)(Bs + k*BR3 + c4) = rb[p];
            }
        }
    };

    float acc[8][4] = {};
    ldA(0); ldB(0);
    for (int k0 = 0; k0 < K; k0 += 32) {
        stA(); stB();
        __syncthreads();
        if (k0 + 32 < K) { ldA(k0 + 32); ldB(k0 + 32); }
#pragma unroll
        for (int kk = 0; kk < 32; kk++) {
            float4 a0 = *(float4*)(As + kk*AR3 + m0);
            float4 a1 = *(float4*)(As + kk*AR3 + m0 + 4);
            float4 b  = *(float4*)(Bs + kk*BR3 + n0);
            acc[0][0] = fmaf(a0.x,b.x,acc[0][0]); acc[0][1] = fmaf(a0.x,b.y,acc[0][1]);
            acc[0][2] = fmaf(a0.x,b.z,acc[0][2]); acc[0][3] = fmaf(a0.x,b.w,acc[0][3]);
            acc[1][0] = fmaf(a0.y,b.x,acc[1][0]); acc[1][1] = fmaf(a0.y,b.y,acc[1][1]);
            acc[1][2] = fmaf(a0.y,b.z,acc[1][2]); acc[1][3] = fmaf(a0.y,b.w,acc[1][3]);
            acc[2][0] = fmaf(a0.z,b.x,acc[2][0]); acc[2][1] = fmaf(a0.z,b.y,acc[2][1]);
            acc[2][2] = fmaf(a0.z,b.z,acc[2][2]); acc[2][3] = fmaf(a0.z,b.w,acc[2][3]);
            acc[3][0] = fmaf(a0.w,b.x,acc[3][0]); acc[3][1] = fmaf(a0.w,b.y,acc[3][1]);
            acc[3][2] = fmaf(a0.w,b.z,acc[3][2]); acc[3][3] = fmaf(a0.w,b.w,acc[3][3]);
            acc[4][0] = fmaf(a1.x,b.x,acc[4][0]); acc[4][1] = fmaf(a1.x,b.y,acc[4][1]);
            acc[4][2] = fmaf(a1.x,b.z,acc[4][2]); acc[4][3] = fmaf(a1.x,b.w,acc[4][3]);
            acc[5][0] = fmaf(a1.y,b.x,acc[5][0]); acc[5][1] = fmaf(a1.y,b.y,acc[5][1]);
            acc[5][2] = fmaf(a1.y,b.z,acc[5][2]); acc[5][3] = fmaf(a1.y,b.w,acc[5][3]);
            acc[6][0] = fmaf(a1.z,b.x,acc[6][0]); acc[6][1] = fmaf(a1.z,b.y,acc[6][1]);
            acc[6][2] = fmaf(a1.z,b.z,acc[6][2]); acc[6][3] = fmaf(a1.z,b.w,acc[6][3]);
            acc[7][0] = fmaf(a1.w,b.x,acc[7][0]); acc[7][1] = fmaf(a1.w,b.y,acc[7][1]);
            acc[7][2] = fmaf(a1.w,b.z,acc[7][2]); acc[7][3] = fmaf(a1.w,b.w,acc[7][3]);
        }
        __syncthreads();
    }

    float4 bb = make_float4(0.f, 0.f, 0.f, 0.f);
    if (bias) bb = *(const float4*)(bias + bn + n0);
#pragma unroll
    for (int i = 0; i < 8; i++) {
        int m = bm + m0 + i;
        float4 v;
        v.x = acc[i][0] + bb.x; v.y = acc[i][1] + bb.y;
        v.z = acc[i][2] + bb.z; v.w = acc[i][3] + bb.w;
        *(float4*)(C + (size_t)m * ldc + bn + n0) = v;
    }
}

#define SBUF3 (32 * AR3 + 32 * BR3)

// ---------------------------------------------------------------------------
// K1: KEY (tile2, 60), QRY (tile3, 32), QQ (tile3, 32), BFQ (tile2, 16), bias.
// ---------------------------------------------------------------------------
__global__ __launch_bounds__(256)
void k1_proj(const float* __restrict__ memkey, const float* __restrict__ h,
             const float* __restrict__ key_w,  const float* __restrict__ key_b,
             const float* __restrict__ query_w,const float* __restrict__ query_b,
             const float* __restrict__ qq_w,   const float* __restrict__ qq_b,
             const float* __restrict__ kq_w,   const float* __restrict__ kq_b,
             const float* __restrict__ proto_w,const float* __restrict__ proto_b,
             float* __restrict__ KEY, float* __restrict__ QRY, float* __restrict__ QQ,
             float* __restrict__ BFQ, float* __restrict__ BF)
{
    __shared__ __align__(16) float sbuf[SBUF3];
    const int b = blockIdx.x;
    if (b < 60) {
        gemm_tile2<0,1>(memkey, key_w, key_b, KEY, (b/4)*64, (b%4)*64, HID, HID, HID, HID, sbuf);
    } else if (b < 92) {
        int i = b - 60;
        gemm_tile3<1>(h, query_w, query_b, QRY, (i/4)*128, (i%4)*64, HID, HID, HID, HID, sbuf);
    } else if (b < 124) {
        int i = b - 92;
        gemm_tile3<1>(h, qq_w, qq_b, QQ, (i/4)*128, (i%4)*64, HID, HID, HID, HID, sbuf);
    } else if (b < 140) {
        int i = b - 124;
        gemm_tile2<1,1>(kq_w, proto_w, nullptr, BFQ, (i/4)*64, (i%4)*64, HID, HID, 2*HID, HID, sbuf);
    } else {
        const int t = threadIdx.x;
        float s2 = proto_b[t];
        for (int c = 0; c < HID; c++)
            s2 = fmaf(kq_b[c], proto_w[(size_t)t * (2*HID) + c], s2);
        BF[t] = s2;
        if (t < NCLS) g_cnt[t] = 0;
    }
}

// ---------------------------------------------------------------------------
// K2: SC1 (tile3, 120), QHAT (tile3 BM=0, 32), KEYP (tile2, 60). grid 212.
// ---------------------------------------------------------------------------
__global__ __launch_bounds__(256)
void k2_score1(const float* __restrict__ QRY, const float* __restrict__ KEY,
               const float* __restrict__ QQ,  const float* __restrict__ kq_w,
               const float* __restrict__ proto_w,
               float* __restrict__ SC1, float* __restrict__ QHAT, float* __restrict__ KEYP)
{
    __shared__ __align__(16) float sbuf[SBUF3];
    const int b = blockIdx.x;
    if (b < 120) {
        gemm_tile3<1>(QRY, KEY, nullptr, SC1, (b/15)*128, (b%15)*64, HID, HID, HID, NKEYS, sbuf);
    } else if (b < 152) {
        int i = b - 120;
        gemm_tile3<0>(QQ, kq_w, nullptr, QHAT, (i/4)*128, (i%4)*64, HID, HID, HID, HID, sbuf);
    } else {
        int i = b - 152;
        gemm_tile2<0,1>(KEY, proto_w + HID, nullptr, KEYP, (i/4)*64, (i%4)*64, HID, HID, 2*HID, HID, sbuf);
    }
}

// ---------------------------------------------------------------------------
// K3: warp-per-row top-5 of 960 via register lists + shfl symmetric merges.
// Records g_topc for k56.
// ---------------------------------------------------------------------------
__global__ __launch_bounds__(256)
void k3_topk1(const float* __restrict__ SC1, const float* __restrict__ KEYP,
              float* __restrict__ OUTM)
{
    const int lane = threadIdx.x & 31;
    const int n = blockIdx.x * 8 + (threadIdx.x >> 5);

    float lv[TOPK]; int li[TOPK];
#pragma unroll
    for (int j = 0; j < TOPK; j++) { lv[j] = -INFINITY; li[j] = 0x7fffffff; }

    const float* row = SC1 + (size_t)n * NKEYS;
#pragma unroll 6
    for (int i = 0; i < NKEYS / 32; i++) {
        int idx = i * 32 + lane;
        float v = row[idx];
        if (v > lv[TOPK-1]) {
            int p = TOPK - 1;
            while (p > 0 && v > lv[p-1]) { lv[p] = lv[p-1]; li[p] = li[p-1]; p--; }
            lv[p] = v; li[p] = idx;
        }
    }

#pragma unroll
    for (int off = 16; off >= 1; off >>= 1) {
        float pv[TOPK]; int pi[TOPK];
#pragma unroll
        for (int j = 0; j < TOPK; j++) {
            pv[j] = __shfl_xor_sync(0xffffffffu, lv[j], off);
            pi[j] = __shfl_xor_sync(0xffffffffu, li[j], off);
        }
        float ov[TOPK]; int oi[TOPK];
        int pa = 0, pb = 0;
#pragma unroll
        for (int j = 0; j < TOPK; j++) {
            bool ta = (lv[pa] > pv[pb]) || (lv[pa] == pv[pb] && li[pa] < pi[pb]);
            if (ta) { ov[j] = lv[pa]; oi[j] = li[pa]; pa++; }
            else    { ov[j] = pv[pb]; oi[j] = pi[pb]; pb++; }
        }
#pragma unroll
        for (int j = 0; j < TOPK; j++) { lv[j] = ov[j]; li[j] = oi[j]; }
    }

    float w[TOPK];
    float mx = lv[0], den = 0.f;
#pragma unroll
    for (int j = 0; j < TOPK; j++) { w[j] = expf(lv[j] - mx); den += w[j]; }
    float dinv = 1.f / den;
#pragma unroll
    for (int j = 0; j < TOPK; j++) w[j] *= dinv;

    if (lane == 0) {
#pragma unroll
        for (int j = 0; j < TOPK; j++) {
            int c = li[j] / DCS;
            g_topc[n * TOPK + j] = c * CPB;
            int p = atomicAdd(&g_cnt[c], 1);
            g_pairs[c * CAP + p] = n * 8 + j;
        }
    }

#pragma unroll
    for (int i = 0; i < HID / 32; i++) {
        int d = i * 32 + lane;
        float acc = 0.f;
#pragma unroll
        for (int j = 0; j < TOPK; j++)
            acc = fmaf(w[j], KEYP[(size_t)li[j] * HID + d], acc);
        OUTM[(size_t)n * HID + d] = acc;
    }
}

// ---------------------------------------------------------------------------
// K4 v6: class-batched scoring GEMM, split-K(8), B resident in smem.
// Block = (class c, K-eighth kh, m-stripe); K=32 per block, single chunk.
// grid (60, 24): kh = y&7, (y>>3) strides m-tiles by 3.
// smem: Bsh[32][85] 10.9KB + As[32][68] 8.7KB + idx ~ 20KB -> ~8 blocks/SM.
// ---------------------------------------------------------------------------
__global__ __launch_bounds__(256)
void k4_score2(const float* __restrict__ QHAT, const float* __restrict__ rawq,
               float* __restrict__ SC2)
{
    __shared__ float Bsh[32][85];                // [k][q<80]
    __shared__ __align__(16) float As[32][68];   // [k][m<64]
    __shared__ int   spn[64], spj[64];

    const int c = blockIdx.x, tid = threadIdx.x;
    const int kh = blockIdx.y & 7;
    const int ty0 = blockIdx.y >> 3;             // 0..2
    const int kbase = kh * 32;
    const int cnt = g_cnt[c];
    const int tm = tid >> 4, tn = tid & 15;
    const float* rbase = rawq + (size_t)c * CPB * HID;
    float* outb = SC2 + (size_t)kh * NROWS * CAND;

    // ---- B: 80 rows x 32 k, loaded ONCE (640 float4) ----
#pragma unroll
    for (int p = 0; p < 3; p++) {
        int idx = tid + p * 256;
        if (idx < CPB * 8) {
            int q = idx >> 3, c4 = (idx & 7) * 4;
            float4 v = *(const float4*)(rbase + (size_t)q * HID + kbase + c4);
            Bsh[c4+0][q] = v.x; Bsh[c4+1][q] = v.y;
            Bsh[c4+2][q] = v.z; Bsh[c4+3][q] = v.w;
        }
    }

    const int am0 = tid >> 3, ac0 = (tid & 7) * 4;
    const int am1 = (tid + 256) >> 3, ac1 = ((tid + 256) & 7) * 4;

    for (int tt = ty0; tt * 64 < cnt; tt += 3) {
        const int m0 = tt * 64;
        __syncthreads();
        if (tid < 64) {
            int mi = m0 + tid;
            int pm = g_pairs[c * CAP + (mi < cnt ? mi : m0)];
            spn[tid] = pm >> 3; spj[tid] = pm & 7;
        }
        __syncthreads();

        // A: 64 pairs x 32 k (512 float4, 2/thread)
        {
            float4 rA0 = *(const float4*)(QHAT + (size_t)spn[am0] * HID + kbase + ac0);
            float4 rA1 = *(const float4*)(QHAT + (size_t)spn[am1] * HID + kbase + ac1);
            As[ac0+0][am0] = rA0.x; As[ac0+1][am0] = rA0.y;
            As[ac0+2][am0] = rA0.z; As[ac0+3][am0] = rA0.w;
            As[ac1+0][am1] = rA1.x; As[ac1+1][am1] = rA1.y;
            As[ac1+2][am1] = rA1.z; As[ac1+3][am1] = rA1.w;
        }
        __syncthreads();

        float acc[4][5] = {};
#pragma unroll
        for (int kk = 0; kk < 32; kk++) {
            float4 a = *(float4*)&As[kk][tm * 4];
            float b0 = Bsh[kk][tn*5+0], b1 = Bsh[kk][tn*5+1], b2 = Bsh[kk][tn*5+2];
            float b3 = Bsh[kk][tn*5+3], b4 = Bsh[kk][tn*5+4];
            acc[0][0] = fmaf(a.x,b0,acc[0][0]); acc[0][1] = fmaf(a.x,b1,acc[0][1]);
            acc[0][2] = fmaf(a.x,b2,acc[0][2]); acc[0][3] = fmaf(a.x,b3,acc[0][3]);
            acc[0][4] = fmaf(a.x,b4,acc[0][4]);
            acc[1][0] = fmaf(a.y,b0,acc[1][0]); acc[1][1] = fmaf(a.y,b1,acc[1][1]);
            acc[1][2] = fmaf(a.y,b2,acc[1][2]); acc[1][3] = fmaf(a.y,b3,acc[1][3]);
            acc[1][4] = fmaf(a.y,b4,acc[1][4]);
            acc[2][0] = fmaf(a.z,b0,acc[2][0]); acc[2][1] = fmaf(a.z,b1,acc[2][1]);
            acc[2][2] = fmaf(a.z,b2,acc[2][2]); acc[2][3] = fmaf(a.z,b3,acc[2][3]);
            acc[2][4] = fmaf(a.z,b4,acc[2][4]);
            acc[3][0] = fmaf(a.w,b0,acc[3][0]); acc[3][1] = fmaf(a.w,b1,acc[3][1]);
            acc[3][2] = fmaf(a.w,b2,acc[3][2]); acc[3][3] = fmaf(a.w,b3,acc[3][3]);
            acc[3][4] = fmaf(a.w,b4,acc[3][4]);
        }
#pragma unroll
        for (int i = 0; i < 4; i++) {
            int m = tm * 4 + i;
            if (m0 + m < cnt) {
                float* dst = outb + (size_t)spn[m] * CAND + spj[m] * CPB + tn * 5;
#pragma unroll
                for (int jq = 0; jq < 5; jq++) dst[jq] = acc[i][jq];
            }
        }
    }
}

// ---------------------------------------------------------------------------
// K56: fused per-row select + weighted gather-sum (sums KSPLIT slabs).
// ---------------------------------------------------------------------------
__global__ __launch_bounds__(256)
void k56_select_wsum(const float* __restrict__ SC2, const float* __restrict__ rawq,
                     float* __restrict__ QSUM)
{
    __shared__ float sc[CAND];
    __shared__ float sb[512];
    __shared__ float rr[256];
    __shared__ int   ii[256];
    __shared__ int   ta[512], tb[512];
    __shared__ int   selrow[TOPKQ];
    __shared__ float selw[TOPKQ];
    __shared__ int   cls[TOPK];
    __shared__ float s_den;
    __shared__ int   s_G;

    const int n = blockIdx.x, tid = threadIdx.x;

    if (tid < TOPK) cls[tid] = g_topc[n * TOPK + tid];
    {
        float v0 = 0.f, v1 = 0.f;
#pragma unroll
        for (int s = 0; s < KSPLIT; s++) {
            const float* slab = SC2 + (size_t)s * NROWS * CAND + (size_t)n * CAND;
            v0 += slab[tid];
            if (tid < CAND - 256) v1 += slab[tid + 256];
        }
        sc[tid] = v0;
        if (tid < CAND - 256) sc[tid + 256] = v1;
    }
    __syncthreads();

    sb[tid] = sc[tid];
    sb[tid + 256] = (tid < CAND - 256) ? sc[tid + 256] : -INFINITY;
    __syncthreads();
    for (int k = 2; k <= 512; k <<= 1) {
        for (int j = k >> 1; j > 0; j >>= 1) {
#pragma unroll
            for (int t = 0; t < 2; t++) {
                int i = tid + t * 256;
                int ixj = i ^ j;
                if (ixj > i) {
                    float a = sb[i], b = sb[ixj];
                    if ((a > b) == ((i & k) == 0)) { sb[i] = b; sb[ixj] = a; }
                }
            }
            __syncthreads();
        }
    }
    const float T  = sb[512 - TOPKQ];
    const float mx = sb[511];

    {
        int cnt = 0; float den = 0.f;
        float v = sc[tid];
        if (v > T) { cnt++; den += expf(v - mx); }
        if (tid < CAND - 256) {
            float v2 = sc[tid + 256];
            if (v2 > T) { cnt++; den += expf(v2 - mx); }
        }
        rr[tid] = den; ii[tid] = cnt;
    }
    __syncthreads();
    for (int off = 128; off > 0; off >>= 1) {
        if (tid < off) { rr[tid] += rr[tid + off]; ii[tid] += ii[tid + off]; }
        __syncthreads();
    }
    if (tid == 0) {
        s_G = ii[0];
        s_den = rr[0] + (float)(TOPKQ - ii[0]) * expf(T - mx);
    }
    __syncthreads();
    const int   G = s_G;
    const float dinv = 1.f / s_den;

    ta[tid]       = (sc[tid] > T) ? 1 : 0;
    ta[tid + 256] = (tid < CAND - 256 && sc[tid + 256] > T) ? 1 : 0;
    __syncthreads();
    {
        int* src = ta; int* dst = tb;
        for (int d = 1; d < 512; d <<= 1) {
            dst[tid]       = src[tid]       + (tid >= d ? src[tid - d] : 0);
            dst[tid + 256] = src[tid + 256] + (tid + 256 >= d ? src[tid + 256 - d] : 0);
            __syncthreads();
            int* t = src; src = dst; dst = t;
        }
#pragma unroll
        for (int t = 0; t < 2; t++) {
            int m = tid + t * 256;
            if (m < CAND && sc[m] > T) {
                int p = src[m] - 1;
                selrow[p] = cls[m / CPB] + (m % CPB);
                selw[p]   = expf(sc[m] - mx) * dinv;
            }
        }
    }
    __syncthreads();

    ta[tid]       = (sc[tid] == T) ? 1 : 0;
    ta[tid + 256] = (tid < CAND - 256 && sc[tid + 256] == T) ? 1 : 0;
    __syncthreads();
    {
        int* src = ta; int* dst = tb;
        for (int d = 1; d < 512; d <<= 1) {
            dst[tid]       = src[tid]       + (tid >= d ? src[tid - d] : 0);
            dst[tid + 256] = src[tid + 256] + (tid + 256 >= d ? src[tid + 256 - d] : 0);
            __syncthreads();
            int* t = src; src = dst; dst = t;
        }
        const float wT = expf(T - mx) * dinv;
#pragma unroll
        for (int t = 0; t < 2; t++) {
            int m = tid + t * 256;
            if (m < CAND && sc[m] == T) {
                int r = src[m] - 1;
                if (r < TOPKQ - G) {
                    selrow[G + r] = cls[m / CPB] + (m % CPB);
                    selw[G + r]   = wT;
                }
            }
        }
    }
    __syncthreads();

    float acc0 = 0.f, acc1 = 0.f, acc2 = 0.f, acc3 = 0.f;
    for (int p = 0; p < TOPKQ; p += 4) {
        acc0 = fmaf(selw[p + 0], rawq[(size_t)selrow[p + 0] * HID + tid], acc0);
        acc1 = fmaf(selw[p + 1], rawq[(size_t)selrow[p + 1] * HID + tid], acc1);
        acc2 = fmaf(selw[p + 2], rawq[(size_t)selrow[p + 2] * HID + tid], acc2);
        acc3 = fmaf(selw[p + 3], rawq[(size_t)selrow[p + 3] * HID + tid], acc3);
    }
    QSUM[(size_t)n * HID + tid] = (acc0 + acc1) + (acc2 + acc3);
}

// ---------------------------------------------------------------------------
// K7: out = QSUM @ BfQ + OUTM + bf.  tile 64m x 32n, grid (8, 16)
// ---------------------------------------------------------------------------
__global__ __launch_bounds__(256)
void k7_out(const float* __restrict__ QSUM, const float* __restrict__ BFQ,
            const float* __restrict__ OUTM, const float* __restrict__ BF,
            float* __restrict__ out)
{
    __shared__ float As[32][65];
    __shared__ float Bsh[32][36];
    const int tid = threadIdx.x;
    const int bm = blockIdx.y * 64, bn = blockIdx.x * 32;
    const int ty = tid >> 3, tx = tid & 7;

    float acc[2][4] = {};
    for (int k0 = 0; k0 < HID; k0 += 32) {
        __syncthreads();
        {
            int r = tid >> 3, c4 = (tid & 7) * 4;
#pragma unroll
            for (int h = 0; h < 2; h++) {
                int m = bm + r + h * 32;
                float4 v = *(const float4*)(QSUM + (size_t)m * HID + k0 + c4);
                As[c4+0][r + h*32] = v.x; As[c4+1][r + h*32] = v.y;
                As[c4+2][r + h*32] = v.z; As[c4+3][r + h*32] = v.w;
            }
        }
        {
            int k = tid >> 3, c4 = (tid & 7) * 4;
            *(float4*)&Bsh[k][c4] = *(const float4*)(BFQ + (size_t)(k0 + k) * HID + bn + c4);
        }
        __syncthreads();
#pragma unroll
        for (int kk = 0; kk < 32; kk++) {
            float a0 = As[kk][ty*2 + 0], a1 = As[kk][ty*2 + 1];
            float4 b = *(float4*)&Bsh[kk][tx*4];
            acc[0][0] = fmaf(a0,b.x,acc[0][0]); acc[0][1] = fmaf(a0,b.y,acc[0][1]);
            acc[0][2] = fmaf(a0,b.z,acc[0][2]); acc[0][3] = fmaf(a0,b.w,acc[0][3]);
            acc[1][0] = fmaf(a1,b.x,acc[1][0]); acc[1][1] = fmaf(a1,b.y,acc[1][1]);
            acc[1][2] = fmaf(a1,b.z,acc[1][2]); acc[1][3] = fmaf(a1,b.w,acc[1][3]);
        }
    }

    float4 bb = *(const float4*)(BF + bn + tx * 4);
#pragma unroll
    for (int i = 0; i < 2; i++) {
        int m = bm + ty * 2 + i;
        float4 om = *(const float4*)(OUTM + (size_t)m * HID + bn + tx * 4);
        float4 v;
        v.x = acc[i][0] + bb.x + om.x; v.y = acc[i][1] + bb.y + om.y;
        v.z = acc[i][2] + bb.z + om.z; v.w = acc[i][3] + bb.w + om.w;
        *(float4*)(out + (size_t)m * HID + bn + tx * 4) = v;
    }
}

// ---------------------------------------------------------------------------
extern "C" void kernel_launch(void* const* d_in, const int* in_sizes, int n_in,
                              void* d_out, int out_size)
{
    const int sh = (n_in >= 15) ? 0 : 1;
    const float* h          = (const float*)d_in[0];
    const float* memory_key = (const float*)d_in[3 - sh];
    const float* queue_key  = (const float*)d_in[4 - sh];
    const float* key_w      = (const float*)d_in[5 - sh];
    const float* key_b      = (const float*)d_in[6 - sh];
    const float* query_w    = (const float*)d_in[7 - sh];
    const float* query_b    = (const float*)d_in[8 - sh];
    const float* kq_w       = (const float*)d_in[9 - sh];
    const float* kq_b       = (const float*)d_in[10 - sh];
    const float* qq_w       = (const float*)d_in[11 - sh];
    const float* qq_b       = (const float*)d_in[12 - sh];
    const float* proto_w    = (const float*)d_in[13 - sh];
    const float* proto_b    = (const float*)d_in[14 - sh];
    float* out = (float*)d_out;

    void* sp = nullptr; cudaGetSymbolAddress(&sp, g_scratch);
    float* S = (float*)sp;
    float* KEY  = S + OFF_KEY;
    float* QRY  = S + OFF_QRY;
    float* QQ   = S + OFF_QQ;
    float* QHAT = S + OFF_QHAT;
    float* KEYP = S + OFF_KEYP;
    float* SC1  = S + OFF_SC1;
    float* SC2  = S + OFF_SC2;
    float* QSUM = S + OFF_QSUM;
    float* OUTM = S + OFF_OUTM;
    float* BFQ  = S + OFF_BFQ;
    float* BF   = S + OFF_BF;

    k1_proj<<<141, 256>>>(memory_key, h, key_w, key_b, query_w, query_b,
                          qq_w, qq_b, kq_w, kq_b, proto_w, proto_b,
                          KEY, QRY, QQ, BFQ, BF);
    k2_score1<<<212, 256>>>(QRY, KEY, QQ, kq_w, proto_w, SC1, QHAT, KEYP);
    k3_topk1<<<NROWS / 8, 256>>>(SC1, KEYP, OUTM);
    k4_score2<<<dim3(60, 24), 256>>>(QHAT, queue_key, SC2);
    k56_select_wsum<<<NROWS, 256>>>(SC2, queue_key, QSUM);
    k7_out<<<dim3(8, 16), 256>>>(QSUM, BFQ, OUTM, BF, out);
}

// round 15
// speedup vs baseline: 1.0381x; 1.0098x over previous
#include <cuda_runtime.h>
#include <math.h>

#define HID    256
#define BS     64
#define DCS    16
#define NCLS   60
#define QSZ    5
#define TOPK   5
#define TOPKQ  100
#define NROWS  (BS * DCS)          // 1024
#define NKEYS  (NCLS * DCS)        // 960
#define CAND   (TOPK * QSZ * DCS)  // 400
#define CPB    (QSZ * DCS)         // 80
#define CAP    (NROWS * TOPK)      // 5120
#define KSPLIT 8

// ---------------------------------------------------------------------------
#define OFF_KEY   0
#define OFF_QRY   (OFF_KEY  + NKEYS*HID)
#define OFF_QQ    (OFF_QRY  + NROWS*HID)
#define OFF_QHAT  (OFF_QQ   + NROWS*HID)
#define OFF_KEYP  (OFF_QHAT + NROWS*HID)
#define OFF_SC1   (OFF_KEYP + NKEYS*HID)
#define OFF_SC2   (OFF_SC1  + NROWS*NKEYS)
#define OFF_QSUM  (OFF_SC2  + KSPLIT*NROWS*CAND)
#define OFF_OUTM  (OFF_QSUM + NROWS*HID)
#define OFF_BFQ   (OFF_OUTM + NROWS*HID)
#define OFF_BF    (OFF_BFQ  + HID*HID)
#define SCRATCH_F (OFF_BF   + HID)

__device__ float g_scratch[SCRATCH_F];
__device__ int   g_pairs[NCLS * CAP];
__device__ int   g_cnt[NCLS];
__device__ int   g_topc[NROWS * TOPK];

#define SROW 68
#define AR3 132
#define BR3 68
#define STAGE2 (32 * SROW + 32 * SROW)   // tile2 stage floats
#define STAGE3 (32 * AR3 + 32 * BR3)     // tile3 stage floats
#define DBUF_FLOATS (2 * STAGE3)         // 12800 floats = 51200 B (covers tile2 too)
#define DBUF_BYTES  (DBUF_FLOATS * 4)

// ---------------------------------------------------------------------------
// tile2 double-buffered: 64x64, BK=32, 4x4/thread, 1 barrier per chunk.
// AM=0: A[M,K]; AM=1: A[K,M]. BM=0: B[K,N]; BM=1: B[N,K].
// ---------------------------------------------------------------------------
template <int AM, int BM>
__device__ __forceinline__ void gemm_tile2(
    const float* __restrict__ A, const float* __restrict__ B,
    const float* __restrict__ bias, float* __restrict__ C,
    int bm, int bn, int K, int lda, int ldb, int ldc, float* sbuf)
{
    const int tid = threadIdx.x;
    const int tx = tid & 15, ty = tid >> 4;

    float4 ra0, ra1, rb0, rb1;

    auto ldA = [&](int k0) {
        if constexpr (AM == 0) {
            int r = tid >> 3, c = (tid & 7) * 4;
            ra0 = *(const float4*)(A + (size_t)(bm + r)      * lda + k0 + c);
            ra1 = *(const float4*)(A + (size_t)(bm + r + 32) * lda + k0 + c);
        } else {
            int k = tid >> 4, c = (tid & 15) * 4;
            ra0 = *(const float4*)(A + (size_t)(k0 + k)      * lda + bm + c);
            ra1 = *(const float4*)(A + (size_t)(k0 + k + 16) * lda + bm + c);
        }
    };
    auto stA = [&](float* As) {
        if constexpr (AM == 0) {
            int r = tid >> 3, c = (tid & 7) * 4;
            As[(c+0)*SROW + r] = ra0.x; As[(c+1)*SROW + r] = ra0.y;
            As[(c+2)*SROW + r] = ra0.z; As[(c+3)*SROW + r] = ra0.w;
            As[(c+0)*SROW + r+32] = ra1.x; As[(c+1)*SROW + r+32] = ra1.y;
            As[(c+2)*SROW + r+32] = ra1.z; As[(c+3)*SROW + r+32] = ra1.w;
        } else {
            int k = tid >> 4, c = (tid & 15) * 4;
            *(float4*)(As + k*SROW + c)      = ra0;
            *(float4*)(As + (k+16)*SROW + c) = ra1;
        }
    };
    auto ldB = [&](int k0) {
        if constexpr (BM == 1) {
            int r = tid >> 3, c = (tid & 7) * 4;
            rb0 = *(const float4*)(B + (size_t)(bn + r)      * ldb + k0 + c);
            rb1 = *(const float4*)(B + (size_t)(bn + r + 32) * ldb + k0 + c);
        } else {
            int k = tid >> 4, c = (tid & 15) * 4;
            rb0 = *(const float4*)(B + (size_t)(k0 + k)      * ldb + bn + c);
            rb1 = *(const float4*)(B + (size_t)(k0 + k + 16) * ldb + bn + c);
        }
    };
    auto stB = [&](float* Bs) {
        if constexpr (BM == 1) {
            int r = tid >> 3, c = (tid & 7) * 4;
            Bs[(c+0)*SROW + r] = rb0.x; Bs[(c+1)*SROW + r] = rb0.y;
            Bs[(c+2)*SROW + r] = rb0.z; Bs[(c+3)*SROW + r] = rb0.w;
            Bs[(c+0)*SROW + r+32] = rb1.x; Bs[(c+1)*SROW + r+32] = rb1.y;
            Bs[(c+2)*SROW + r+32] = rb1.z; Bs[(c+3)*SROW + r+32] = rb1.w;
        } else {
            int k = tid >> 4, c = (tid & 15) * 4;
            *(float4*)(Bs + k*SROW + c)      = rb0;
            *(float4*)(Bs + (k+16)*SROW + c) = rb1;
        }
    };

    float acc[4][4] = {};
    ldA(0); ldB(0);
    int s = 0;
    for (int k0 = 0; k0 < K; k0 += 32) {
        float* As = sbuf + s * STAGE2;
        float* Bs = As + 32 * SROW;
        stA(As); stB(Bs);
        __syncthreads();
        if (k0 + 32 < K) { ldA(k0 + 32); ldB(k0 + 32); }
#pragma unroll
        for (int kk = 0; kk < 32; kk++) {
            float4 a = *(float4*)(As + kk*SROW + ty*4);
            float4 b = *(float4*)(Bs + kk*SROW + tx*4);
            acc[0][0] = fmaf(a.x, b.x, acc[0][0]); acc[0][1] = fmaf(a.x, b.y, acc[0][1]);
            acc[0][2] = fmaf(a.x, b.z, acc[0][2]); acc[0][3] = fmaf(a.x, b.w, acc[0][3]);
            acc[1][0] = fmaf(a.y, b.x, acc[1][0]); acc[1][1] = fmaf(a.y, b.y, acc[1][1]);
            acc[1][2] = fmaf(a.y, b.z, acc[1][2]); acc[1][3] = fmaf(a.y, b.w, acc[1][3]);
            acc[2][0] = fmaf(a.z, b.x, acc[2][0]); acc[2][1] = fmaf(a.z, b.y, acc[2][1]);
            acc[2][2] = fmaf(a.z, b.z, acc[2][2]); acc[2][3] = fmaf(a.z, b.w, acc[2][3]);
            acc[3][0] = fmaf(a.w, b.x, acc[3][0]); acc[3][1] = fmaf(a.w, b.y, acc[3][1]);
            acc[3][2] = fmaf(a.w, b.z, acc[3][2]); acc[3][3] = fmaf(a.w, b.w, acc[3][3]);
        }
        s ^= 1;
    }

    float4 bb = make_float4(0.f, 0.f, 0.f, 0.f);
    if (bias) bb = *(const float4*)(bias + bn + tx * 4);
#pragma unroll
    for (int i = 0; i < 4; i++) {
        int m = bm + ty * 4 + i;
        float4 v;
        v.x = acc[i][0] + bb.x; v.y = acc[i][1] + bb.y;
        v.z = acc[i][2] + bb.z; v.w = acc[i][3] + bb.w;
        *(float4*)(C + (size_t)m * ldc + bn + tx * 4) = v;
    }
}

// ---------------------------------------------------------------------------
// tile3 double-buffered: 128x64, BK=32, 8x4/thread, 1 barrier per chunk.
// ---------------------------------------------------------------------------
template <int BM>
__device__ __forceinline__ void gemm_tile3(
    const float* __restrict__ A, const float* __restrict__ B,
    const float* __restrict__ bias, float* __restrict__ C,
    int bm, int bn, int K, int lda, int ldb, int ldc, float* sbuf)
{
    const int tid = threadIdx.x;
    const int tx = tid & 15, ty = tid >> 4;
    const int m0 = ty * 8, n0 = tx * 4;

    float4 ra[4], rb[2];
    auto ldA = [&](int k0) {
#pragma unroll
        for (int p = 0; p < 4; p++) {
            int idx = tid + p * 256;
            int r = idx >> 3, c4 = (idx & 7) * 4;
            ra[p] = *(const float4*)(A + (size_t)(bm + r) * lda + k0 + c4);
        }
    };
    auto stA = [&](float* As) {
#pragma unroll
        for (int p = 0; p < 4; p++) {
            int idx = tid + p * 256;
            int r = idx >> 3, c4 = (idx & 7) * 4;
            As[(c4+0)*AR3 + r] = ra[p].x; As[(c4+1)*AR3 + r] = ra[p].y;
            As[(c4+2)*AR3 + r] = ra[p].z; As[(c4+3)*AR3 + r] = ra[p].w;
        }
    };
    auto ldB = [&](int k0) {
        if constexpr (BM == 1) {
#pragma unroll
            for (int p = 0; p < 2; p++) {
                int idx = tid + p * 256;
                int r = idx >> 3, c4 = (idx & 7) * 4;
                rb[p] = *(const float4*)(B + (size_t)(bn + r) * ldb + k0 + c4);
            }
        } else {
#pragma unroll
            for (int p = 0; p < 2; p++) {
                int idx = tid + p * 256;
                int k = idx >> 4, c4 = (idx & 15) * 4;
                rb[p] = *(const float4*)(B + (size_t)(k0 + k) * ldb + bn + c4);
            }
        }
    };
    auto stB = [&](float* Bs) {
        if constexpr (BM == 1) {
#pragma unroll
            for (int p = 0; p < 2; p++) {
                int idx = tid + p * 256;
                int r = idx >> 3, c4 = (idx & 7) * 4;
                Bs[(c4+0)*BR3 + r] = rb[p].x; Bs[(c4+1)*BR3 + r] = rb[p].y;
                Bs[(c4+2)*BR3 + r] = rb[p].z; Bs[(c4+3)*BR3 + r] = rb[p].w;
            }
        } else {
#pragma unroll
            for (int p = 0; p < 2; p++) {
                int idx = tid + p * 256;
                int k = idx >> 4, c4 = (idx & 15) * 4;
                *(float4*)(Bs + k*BR3 + c4) = rb[p];
            }
        }
    };

    float acc[8][4] = {};
    ldA(0); ldB(0);
    int s = 0;
    for (int k0 = 0; k0 < K; k0 += 32) {
        float* As = sbuf + s * STAGE3;
        float* Bs = As + 32 * AR3;
        stA(As); stB(Bs);
        __syncthreads();
        if (k0 + 32 < K) { ldA(k0 + 32); ldB(k0 + 32); }
#pragma unroll
        for (int kk = 0; kk < 32; kk++) {
            float4 a0 = *(float4*)(As + kk*AR3 + m0);
            float4 a1 = *(float4*)(As + kk*AR3 + m0 + 4);
            float4 b  = *(float4*)(Bs + kk*BR3 + n0);
            acc[0][0] = fmaf(a0.x,b.x,acc[0][0]); acc[0][1] = fmaf(a0.x,b.y,acc[0][1]);
            acc[0][2] = fmaf(a0.x,b.z,acc[0][2]); acc[0][3] = fmaf(a0.x,b.w,acc[0][3]);
            acc[1][0] = fmaf(a0.y,b.x,acc[1][0]); acc[1][1] = fmaf(a0.y,b.y,acc[1][1]);
            acc[1][2] = fmaf(a0.y,b.z,acc[1][2]); acc[1][3] = fmaf(a0.y,b.w,acc[1][3]);
            acc[2][0] = fmaf(a0.z,b.x,acc[2][0]); acc[2][1] = fmaf(a0.z,b.y,acc[2][1]);
            acc[2][2] = fmaf(a0.z,b.z,acc[2][2]); acc[2][3] = fmaf(a0.z,b.w,acc[2][3]);
            acc[3][0] = fmaf(a0.w,b.x,acc[3][0]); acc[3][1] = fmaf(a0.w,b.y,acc[3][1]);
            acc[3][2] = fmaf(a0.w,b.z,acc[3][2]); acc[3][3] = fmaf(a0.w,b.w,acc[3][3]);
            acc[4][0] = fmaf(a1.x,b.x,acc[4][0]); acc[4][1] = fmaf(a1.x,b.y,acc[4][1]);
            acc[4][2] = fmaf(a1.x,b.z,acc[4][2]); acc[4][3] = fmaf(a1.x,b.w,acc[4][3]);
            acc[5][0] = fmaf(a1.y,b.x,acc[5][0]); acc[5][1] = fmaf(a1.y,b.y,acc[5][1]);
            acc[5][2] = fmaf(a1.y,b.z,acc[5][2]); acc[5][3] = fmaf(a1.y,b.w,acc[5][3]);
            acc[6][0] = fmaf(a1.z,b.x,acc[6][0]); acc[6][1] = fmaf(a1.z,b.y,acc[6][1]);
            acc[6][2] = fmaf(a1.z,b.z,acc[6][2]); acc[6][3] = fmaf(a1.z,b.w,acc[6][3]);
            acc[7][0] = fmaf(a1.w,b.x,acc[7][0]); acc[7][1] = fmaf(a1.w,b.y,acc[7][1]);
            acc[7][2] = fmaf(a1.w,b.z,acc[7][2]); acc[7][3] = fmaf(a1.w,b.w,acc[7][3]);
        }
        s ^= 1;
    }

    float4 bb = make_float4(0.f, 0.f, 0.f, 0.f);
    if (bias) bb = *(const float4*)(bias + bn + n0);
#pragma unroll
    for (int i = 0; i < 8; i++) {
        int m = bm + m0 + i;
        float4 v;
        v.x = acc[i][0] + bb.x; v.y = acc[i][1] + bb.y;
        v.z = acc[i][2] + bb.z; v.w = acc[i][3] + bb.w;
        *(float4*)(C + (size_t)m * ldc + bn + n0) = v;
    }
}

// ---------------------------------------------------------------------------
// K1: KEY (tile2, 60), QRY (tile3, 32), QQ (tile3, 32), BFQ (tile2, 16), bias.
// dynamic smem DBUF_BYTES.
// ---------------------------------------------------------------------------
__global__ __launch_bounds__(256)
void k1_proj(const float* __restrict__ memkey, const float* __restrict__ h,
             const float* __restrict__ key_w,  const float* __restrict__ key_b,
             const float* __restrict__ query_w,const float* __restrict__ query_b,
             const float* __restrict__ qq_w,   const float* __restrict__ qq_b,
             const float* __restrict__ kq_w,   const float* __restrict__ kq_b,
             const float* __restrict__ proto_w,const float* __restrict__ proto_b,
             float* __restrict__ KEY, float* __restrict__ QRY, float* __restrict__ QQ,
             float* __restrict__ BFQ, float* __restrict__ BF)
{
    extern __shared__ __align__(16) float dbuf[];
    const int b = blockIdx.x;
    if (b < 60) {
        gemm_tile2<0,1>(memkey, key_w, key_b, KEY, (b/4)*64, (b%4)*64, HID, HID, HID, HID, dbuf);
    } else if (b < 92) {
        int i = b - 60;
        gemm_tile3<1>(h, query_w, query_b, QRY, (i/4)*128, (i%4)*64, HID, HID, HID, HID, dbuf);
    } else if (b < 124) {
        int i = b - 92;
        gemm_tile3<1>(h, qq_w, qq_b, QQ, (i/4)*128, (i%4)*64, HID, HID, HID, HID, dbuf);
    } else if (b < 140) {
        int i = b - 124;
        gemm_tile2<1,1>(kq_w, proto_w, nullptr, BFQ, (i/4)*64, (i%4)*64, HID, HID, 2*HID, HID, dbuf);
    } else {
        const int t = threadIdx.x;
        float s2 = proto_b[t];
        for (int c = 0; c < HID; c++)
            s2 = fmaf(kq_b[c], proto_w[(size_t)t * (2*HID) + c], s2);
        BF[t] = s2;
        if (t < NCLS) g_cnt[t] = 0;
    }
}

// ---------------------------------------------------------------------------
// K2: SC1 (tile3, 120), QHAT (tile3 BM=0, 32), KEYP (tile2, 60). grid 212.
// ---------------------------------------------------------------------------
__global__ __launch_bounds__(256)
void k2_score1(const float* __restrict__ QRY, const float* __restrict__ KEY,
               const float* __restrict__ QQ,  const float* __restrict__ kq_w,
               const float* __restrict__ proto_w,
               float* __restrict__ SC1, float* __restrict__ QHAT, float* __restrict__ KEYP)
{
    extern __shared__ __align__(16) float dbuf[];
    const int b = blockIdx.x;
    if (b < 120) {
        gemm_tile3<1>(QRY, KEY, nullptr, SC1, (b/15)*128, (b%15)*64, HID, HID, HID, NKEYS, dbuf);
    } else if (b < 152) {
        int i = b - 120;
        gemm_tile3<0>(QQ, kq_w, nullptr, QHAT, (i/4)*128, (i%4)*64, HID, HID, HID, HID, dbuf);
    } else {
        int i = b - 152;
        gemm_tile2<0,1>(KEY, proto_w + HID, nullptr, KEYP, (i/4)*64, (i%4)*64, HID, HID, 2*HID, HID, dbuf);
    }
}

// ---------------------------------------------------------------------------
// K3: warp-per-row top-5 via register lists + shfl merges. Records g_topc.
// ---------------------------------------------------------------------------
__global__ __launch_bounds__(256)
void k3_topk1(const float* __restrict__ SC1, const float* __restrict__ KEYP,
              float* __restrict__ OUTM)
{
    const int lane = threadIdx.x & 31;
    const int n = blockIdx.x * 8 + (threadIdx.x >> 5);

    float lv[TOPK]; int li[TOPK];
#pragma unroll
    for (int j = 0; j < TOPK; j++) { lv[j] = -INFINITY; li[j] = 0x7fffffff; }

    const float* row = SC1 + (size_t)n * NKEYS;
#pragma unroll 6
    for (int i = 0; i < NKEYS / 32; i++) {
        int idx = i * 32 + lane;
        float v = row[idx];
        if (v > lv[TOPK-1]) {
            int p = TOPK - 1;
            while (p > 0 && v > lv[p-1]) { lv[p] = lv[p-1]; li[p] = li[p-1]; p--; }
            lv[p] = v; li[p] = idx;
        }
    }

#pragma unroll
    for (int off = 16; off >= 1; off >>= 1) {
        float pv[TOPK]; int pi[TOPK];
#pragma unroll
        for (int j = 0; j < TOPK; j++) {
            pv[j] = __shfl_xor_sync(0xffffffffu, lv[j], off);
            pi[j] = __shfl_xor_sync(0xffffffffu, li[j], off);
        }
        float ov[TOPK]; int oi[TOPK];
        int pa = 0, pb = 0;
#pragma unroll
        for (int j = 0; j < TOPK; j++) {
            bool ta = (lv[pa] > pv[pb]) || (lv[pa] == pv[pb] && li[pa] < pi[pb]);
            if (ta) { ov[j] = lv[pa]; oi[j] = li[pa]; pa++; }
            else    { ov[j] = pv[pb]; oi[j] = pi[pb]; pb++; }
        }
#pragma unroll
        for (int j = 0; j < TOPK; j++) { lv[j] = ov[j]; li[j] = oi[j]; }
    }

    float w[TOPK];
    float mx = lv[0], den = 0.f;
#pragma unroll
    for (int j = 0; j < TOPK; j++) { w[j] = expf(lv[j] - mx); den += w[j]; }
    float dinv = 1.f / den;
#pragma unroll
    for (int j = 0; j < TOPK; j++) w[j] *= dinv;

    if (lane == 0) {
#pragma unroll
        for (int j = 0; j < TOPK; j++) {
            int c = li[j] / DCS;
            g_topc[n * TOPK + j] = c * CPB;
            int p = atomicAdd(&g_cnt[c], 1);
            g_pairs[c * CAP + p] = n * 8 + j;
        }
    }

#pragma unroll
    for (int i = 0; i < HID / 32; i++) {
        int d = i * 32 + lane;
        float acc = 0.f;
#pragma unroll
        for (int j = 0; j < TOPK; j++)
            acc = fmaf(w[j], KEYP[(size_t)li[j] * HID + d], acc);
        OUTM[(size_t)n * HID + d] = acc;
    }
}

// ---------------------------------------------------------------------------
// K4 v6: class-batched scoring GEMM, split-K(8), B resident. grid (60, 24).
// ---------------------------------------------------------------------------
__global__ __launch_bounds__(256)
void k4_score2(const float* __restrict__ QHAT, const float* __restrict__ rawq,
               float* __restrict__ SC2)
{
    __shared__ float Bsh[32][85];
    __shared__ __align__(16) float As[32][68];
    __shared__ int   spn[64], spj[64];

    const int c = blockIdx.x, tid = threadIdx.x;
    const int kh = blockIdx.y & 7;
    const int ty0 = blockIdx.y >> 3;
    const int kbase = kh * 32;
    const int cnt = g_cnt[c];
    const int tm = tid >> 4, tn = tid & 15;
    const float* rbase = rawq + (size_t)c * CPB * HID;
    float* outb = SC2 + (size_t)kh * NROWS * CAND;

#pragma unroll
    for (int p = 0; p < 3; p++) {
        int idx = tid + p * 256;
        if (idx < CPB * 8) {
            int q = idx >> 3, c4 = (idx & 7) * 4;
            float4 v = *(const float4*)(rbase + (size_t)q * HID + kbase + c4);
            Bsh[c4+0][q] = v.x; Bsh[c4+1][q] = v.y;
            Bsh[c4+2][q] = v.z; Bsh[c4+3][q] = v.w;
        }
    }

    const int am0 = tid >> 3, ac0 = (tid & 7) * 4;
    const int am1 = (tid + 256) >> 3, ac1 = ((tid + 256) & 7) * 4;

    for (int tt = ty0; tt * 64 < cnt; tt += 3) {
        const int m0 = tt * 64;
        __syncthreads();
        if (tid < 64) {
            int mi = m0 + tid;
            int pm = g_pairs[c * CAP + (mi < cnt ? mi : m0)];
            spn[tid] = pm >> 3; spj[tid] = pm & 7;
        }
        __syncthreads();

        {
            float4 rA0 = *(const float4*)(QHAT + (size_t)spn[am0] * HID + kbase + ac0);
            float4 rA1 = *(const float4*)(QHAT + (size_t)spn[am1] * HID + kbase + ac1);
            As[ac0+0][am0] = rA0.x; As[ac0+1][am0] = rA0.y;
            As[ac0+2][am0] = rA0.z; As[ac0+3][am0] = rA0.w;
            As[ac1+0][am1] = rA1.x; As[ac1+1][am1] = rA1.y;
            As[ac1+2][am1] = rA1.z; As[ac1+3][am1] = rA1.w;
        }
        __syncthreads();

        float acc[4][5] = {};
#pragma unroll
        for (int kk = 0; kk < 32; kk++) {
            float4 a = *(float4*)&As[kk][tm * 4];
            float b0 = Bsh[kk][tn*5+0], b1 = Bsh[kk][tn*5+1], b2 = Bsh[kk][tn*5+2];
            float b3 = Bsh[kk][tn*5+3], b4 = Bsh[kk][tn*5+4];
            acc[0][0] = fmaf(a.x,b0,acc[0][0]); acc[0][1] = fmaf(a.x,b1,acc[0][1]);
            acc[0][2] = fmaf(a.x,b2,acc[0][2]); acc[0][3] = fmaf(a.x,b3,acc[0][3]);
            acc[0][4] = fmaf(a.x,b4,acc[0][4]);
            acc[1][0] = fmaf(a.y,b0,acc[1][0]); acc[1][1] = fmaf(a.y,b1,acc[1][1]);
            acc[1][2] = fmaf(a.y,b2,acc[1][2]); acc[1][3] = fmaf(a.y,b3,acc[1][3]);
            acc[1][4] = fmaf(a.y,b4,acc[1][4]);
            acc[2][0] = fmaf(a.z,b0,acc[2][0]); acc[2][1] = fmaf(a.z,b1,acc[2][1]);
            acc[2][2] = fmaf(a.z,b2,acc[2][2]); acc[2][3] = fmaf(a.z,b3,acc[2][3]);
            acc[2][4] = fmaf(a.z,b4,acc[2][4]);
            acc[3][0] = fmaf(a.w,b0,acc[3][0]); acc[3][1] = fmaf(a.w,b1,acc[3][1]);
            acc[3][2] = fmaf(a.w,b2,acc[3][2]); acc[3][3] = fmaf(a.w,b3,acc[3][3]);
            acc[3][4] = fmaf(a.w,b4,acc[3][4]);
        }
#pragma unroll
        for (int i = 0; i < 4; i++) {
            int m = tm * 4 + i;
            if (m0 + m < cnt) {
                float* dst = outb + (size_t)spn[m] * CAND + spj[m] * CPB + tn * 5;
#pragma unroll
                for (int jq = 0; jq < 5; jq++) dst[jq] = acc[i][jq];
            }
        }
    }
}

// ---------------------------------------------------------------------------
// K56: fused per-row select + weighted gather-sum (sums KSPLIT slabs).
// ---------------------------------------------------------------------------
__global__ __launch_bounds__(256)
void k56_select_wsum(const float* __restrict__ SC2, const float* __restrict__ rawq,
                     float* __restrict__ QSUM)
{
    __shared__ float sc[CAND];
    __shared__ float sb[512];
    __shared__ float rr[256];
    __shared__ int   ii[256];
    __shared__ int   ta[512], tb[512];
    __shared__ int   selrow[TOPKQ];
    __shared__ float selw[TOPKQ];
    __shared__ int   cls[TOPK];
    __shared__ float s_den;
    __shared__ int   s_G;

    const int n = blockIdx.x, tid = threadIdx.x;

    if (tid < TOPK) cls[tid] = g_topc[n * TOPK + tid];
    {
        float v0 = 0.f, v1 = 0.f;
#pragma unroll
        for (int s = 0; s < KSPLIT; s++) {
            const float* slab = SC2 + (size_t)s * NROWS * CAND + (size_t)n * CAND;
            v0 += slab[tid];
            if (tid < CAND - 256) v1 += slab[tid + 256];
        }
        sc[tid] = v0;
        if (tid < CAND - 256) sc[tid + 256] = v1;
    }
    __syncthreads();

    sb[tid] = sc[tid];
    sb[tid + 256] = (tid < CAND - 256) ? sc[tid + 256] : -INFINITY;
    __syncthreads();
    for (int k = 2; k <= 512; k <<= 1) {
        for (int j = k >> 1; j > 0; j >>= 1) {
#pragma unroll
            for (int t = 0; t < 2; t++) {
                int i = tid + t * 256;
                int ixj = i ^ j;
                if (ixj > i) {
                    float a = sb[i], b = sb[ixj];
                    if ((a > b) == ((i & k) == 0)) { sb[i] = b; sb[ixj] = a; }
                }
            }
            __syncthreads();
        }
    }
    const float T  = sb[512 - TOPKQ];
    const float mx = sb[511];

    {
        int cnt = 0; float den = 0.f;
        float v = sc[tid];
        if (v > T) { cnt++; den += expf(v - mx); }
        if (tid < CAND - 256) {
            float v2 = sc[tid + 256];
            if (v2 > T) { cnt++; den += expf(v2 - mx); }
        }
        rr[tid] = den; ii[tid] = cnt;
    }
    __syncthreads();
    for (int off = 128; off > 0; off >>= 1) {
        if (tid < off) { rr[tid] += rr[tid + off]; ii[tid] += ii[tid + off]; }
        __syncthreads();
    }
    if (tid == 0) {
        s_G = ii[0];
        s_den = rr[0] + (float)(TOPKQ - ii[0]) * expf(T - mx);
    }
    __syncthreads();
    const int   G = s_G;
    const float dinv = 1.f / s_den;

    ta[tid]       = (sc[tid] > T) ? 1 : 0;
    ta[tid + 256] = (tid < CAND - 256 && sc[tid + 256] > T) ? 1 : 0;
    __syncthreads();
    {
        int* src = ta; int* dst = tb;
        for (int d = 1; d < 512; d <<= 1) {
            dst[tid]       = src[tid]       + (tid >= d ? src[tid - d] : 0);
            dst[tid + 256] = src[tid + 256] + (tid + 256 >= d ? src[tid + 256 - d] : 0);
            __syncthreads();
            int* t = src; src = dst; dst = t;
        }
#pragma unroll
        for (int t = 0; t < 2; t++) {
            int m = tid + t * 256;
            if (m < CAND && sc[m] > T) {
                int p = src[m] - 1;
                selrow[p] = cls[m / CPB] + (m % CPB);
                selw[p]   = expf(sc[m] - mx) * dinv;
            }
        }
    }
    __syncthreads();

    ta[tid]       = (sc[tid] == T) ? 1 : 0;
    ta[tid + 256] = (tid < CAND - 256 && sc[tid + 256] == T) ? 1 : 0;
    __syncthreads();
    {
        int* src = ta; int* dst = tb;
        for (int d = 1; d < 512; d <<= 1) {
            dst[tid]       = src[tid]       + (tid >= d ? src[tid - d] : 0);
            dst[tid + 256] = src[tid + 256] + (tid + 256 >= d ? src[tid + 256 - d] : 0);
            __syncthreads();
            int* t = src; src = dst; dst = t;
        }
        const float wT = expf(T - mx) * dinv;
#pragma unroll
        for (int t = 0; t < 2; t++) {
            int m = tid + t * 256;
            if (m < CAND && sc[m] == T) {
                int r = src[m] - 1;
                if (r < TOPKQ - G) {
                    selrow[G + r] = cls[m / CPB] + (m % CPB);
                    selw[G + r]   = wT;
                }
            }
        }
    }
    __syncthreads();

    float acc0 = 0.f, acc1 = 0.f, acc2 = 0.f, acc3 = 0.f;
    for (int p = 0; p < TOPKQ; p += 4) {
        acc0 = fmaf(selw[p + 0], rawq[(size_t)selrow[p + 0] * HID + tid], acc0);
        acc1 = fmaf(selw[p + 1], rawq[(size_t)selrow[p + 1] * HID + tid], acc1);
        acc2 = fmaf(selw[p + 2], rawq[(size_t)selrow[p + 2] * HID + tid], acc2);
        acc3 = fmaf(selw[p + 3], rawq[(size_t)selrow[p + 3] * HID + tid], acc3);
    }
    QSUM[(size_t)n * HID + tid] = (acc0 + acc1) + (acc2 + acc3);
}

// ---------------------------------------------------------------------------
// K7: out = QSUM @ BfQ + OUTM + bf.  tile 64m x 32n, grid (8, 16)
// ---------------------------------------------------------------------------
__global__ __launch_bounds__(256)
void k7_out(const float* __restrict__ QSUM, const float* __restrict__ BFQ,
            const float* __restrict__ OUTM, const float* __restrict__ BF,
            float* __restrict__ out)
{
    __shared__ float As[32][65];
    __shared__ float Bsh[32][36];
    const int tid = threadIdx.x;
    const int bm = blockIdx.y * 64, bn = blockIdx.x * 32;
    const int ty = tid >> 3, tx = tid & 7;

    float acc[2][4] = {};
    for (int k0 = 0; k0 < HID; k0 += 32) {
        __syncthreads();
        {
            int r = tid >> 3, c4 = (tid & 7) * 4;
#pragma unroll
            for (int h = 0; h < 2; h++) {
                int m = bm + r + h * 32;
                float4 v = *(const float4*)(QSUM + (size_t)m * HID + k0 + c4);
                As[c4+0][r + h*32] = v.x; As[c4+1][r + h*32] = v.y;
                As[c4+2][r + h*32] = v.z; As[c4+3][r + h*32] = v.w;
            }
        }
        {
            int k = tid >> 3, c4 = (tid & 7) * 4;
            *(float4*)&Bsh[k][c4] = *(const float4*)(BFQ + (size_t)(k0 + k) * HID + bn + c4);
        }
        __syncthreads();
#pragma unroll
        for (int kk = 0; kk < 32; kk++) {
            float a0 = As[kk][ty*2 + 0], a1 = As[kk][ty*2 + 1];
            float4 b = *(float4*)&Bsh[kk][tx*4];
            acc[0][0] = fmaf(a0,b.x,acc[0][0]); acc[0][1] = fmaf(a0,b.y,acc[0][1]);
            acc[0][2] = fmaf(a0,b.z,acc[0][2]); acc[0][3] = fmaf(a0,b.w,acc[0][3]);
            acc[1][0] = fmaf(a1,b.x,acc[1][0]); acc[1][1] = fmaf(a1,b.y,acc[1][1]);
            acc[1][2] = fmaf(a1,b.z,acc[1][2]); acc[1][3] = fmaf(a1,b.w,acc[1][3]);
        }
    }

    float4 bb = *(const float4*)(BF + bn + tx * 4);
#pragma unroll
    for (int i = 0; i < 2; i++) {
        int m = bm + ty * 2 + i;
        float4 om = *(const float4*)(OUTM + (size_t)m * HID + bn + tx * 4);
        float4 v;
        v.x = acc[i][0] + bb.x + om.x; v.y = acc[i][1] + bb.y + om.y;
        v.z = acc[i][2] + bb.z + om.z; v.w = acc[i][3] + bb.w + om.w;
        *(float4*)(out + (size_t)m * HID + bn + tx * 4) = v;
    }
}

// ---------------------------------------------------------------------------
extern "C" void kernel_launch(void* const* d_in, const int* in_sizes, int n_in,
                              void* d_out, int out_size)
{
    const int sh = (n_in >= 15) ? 0 : 1;
    const float* h          = (const float*)d_in[0];
    const float* memory_key = (const float*)d_in[3 - sh];
    const float* queue_key  = (const float*)d_in[4 - sh];
    const float* key_w      = (const float*)d_in[5 - sh];
    const float* key_b      = (const float*)d_in[6 - sh];
    const float* query_w    = (const float*)d_in[7 - sh];
    const float* query_b    = (const float*)d_in[8 - sh];
    const float* kq_w       = (const float*)d_in[9 - sh];
    const float* kq_b       = (const float*)d_in[10 - sh];
    const float* qq_w       = (const float*)d_in[11 - sh];
    const float* qq_b       = (const float*)d_in[12 - sh];
    const float* proto_w    = (const float*)d_in[13 - sh];
    const float* proto_b    = (const float*)d_in[14 - sh];
    float* out = (float*)d_out;

    void* sp = nullptr; cudaGetSymbolAddress(&sp, g_scratch);
    float* S = (float*)sp;
    float* KEY  = S + OFF_KEY;
    float* QRY  = S + OFF_QRY;
    float* QQ   = S + OFF_QQ;
    float* QHAT = S + OFF_QHAT;
    float* KEYP = S + OFF_KEYP;
    float* SC1  = S + OFF_SC1;
    float* SC2  = S + OFF_SC2;
    float* QSUM = S + OFF_QSUM;
    float* OUTM = S + OFF_OUTM;
    float* BFQ  = S + OFF_BFQ;
    float* BF   = S + OFF_BF;

    // opt-in to >48KB dynamic smem (idempotent, host-side, capture-safe)
    cudaFuncSetAttribute(k1_proj,   cudaFuncAttributeMaxDynamicSharedMemorySize, DBUF_BYTES);
    cudaFuncSetAttribute(k2_score1, cudaFuncAttributeMaxDynamicSharedMemorySize, DBUF_BYTES);

    k1_proj<<<141, 256, DBUF_BYTES>>>(memory_key, h, key_w, key_b, query_w, query_b,
                                      qq_w, qq_b, kq_w, kq_b, proto_w, proto_b,
                                      KEY, QRY, QQ, BFQ, BF);
    k2_score1<<<212, 256, DBUF_BYTES>>>(QRY, KEY, QQ, kq_w, proto_w, SC1, QHAT, KEYP);
    k3_topk1<<<NROWS / 8, 256>>>(SC1, KEYP, OUTM);
    k4_score2<<<dim3(60, 24), 256>>>(QHAT, queue_key, SC2);
    k56_select_wsum<<<NROWS, 256>>>(SC2, queue_key, QSUM);
    k7_out<<<dim3(8, 16), 256>>>(QSUM, BFQ, OUTM, BF, out);
}

// round 17
// speedup vs baseline: 1.1171x; 1.0761x over previous
#include <cuda_runtime.h>
#include <math.h>

#define HID    256
#define BS     64
#define DCS    16
#define NCLS   60
#define QSZ    5
#define TOPK   5
#define TOPKQ  100
#define NROWS  (BS * DCS)          // 1024
#define NKEYS  (NCLS * DCS)        // 960
#define CAND   (TOPK * QSZ * DCS)  // 400
#define CPB    (QSZ * DCS)         // 80
#define CAP    (NROWS * TOPK)      // 5120
#define KSPLIT 8

// ---------------------------------------------------------------------------
#define OFF_KEY   0
#define OFF_QRY   (OFF_KEY  + NKEYS*HID)
#define OFF_QQ    (OFF_QRY  + NROWS*HID)
#define OFF_QHAT  (OFF_QQ   + NROWS*HID)
#define OFF_KEYP  (OFF_QHAT + NROWS*HID)
#define OFF_SC1   (OFF_KEYP + NKEYS*HID)
#define OFF_SC2   (OFF_SC1  + NROWS*NKEYS)
#define OFF_QSUM  (OFF_SC2  + KSPLIT*NROWS*CAND)
#define OFF_OUTM  (OFF_QSUM + NROWS*HID)
#define OFF_BFQ   (OFF_OUTM + NROWS*HID)
#define OFF_BF    (OFF_BFQ  + HID*HID)
#define SCRATCH_F (OFF_BF   + HID)

__device__ float g_scratch[SCRATCH_F];
__device__ int   g_pairs[NCLS * CAP];
__device__ int   g_cnt[NCLS];
__device__ int   g_topc[NROWS * TOPK];

#define SROW 68
#define AR3 132
#define BR3 68
#define STAGE2 (32 * SROW + 32 * SROW)
#define STAGE3 (32 * AR3 + 32 * BR3)
#define DBUF_FLOATS (2 * STAGE3)
#define DBUF_BYTES  (DBUF_FLOATS * 4)

// ---------------------------------------------------------------------------
// tile2 double-buffered: 64x64, BK=32, 4x4/thread, 1 barrier per chunk.
// ---------------------------------------------------------------------------
template <int AM, int BM>
__device__ __forceinline__ void gemm_tile2(
    const float* __restrict__ A, const float* __restrict__ B,
    const float* __restrict__ bias, float* __restrict__ C,
    int bm, int bn, int K, int lda, int ldb, int ldc, float* sbuf)
{
    const int tid = threadIdx.x;
    const int tx = tid & 15, ty = tid >> 4;

    float4 ra0, ra1, rb0, rb1;

    auto ldA = [&](int k0) {
        if constexpr (AM == 0) {
            int r = tid >> 3, c = (tid & 7) * 4;
            ra0 = *(const float4*)(A + (size_t)(bm + r)      * lda + k0 + c);
            ra1 = *(const float4*)(A + (size_t)(bm + r + 32) * lda + k0 + c);
        } else {
            int k = tid >> 4, c = (tid & 15) * 4;
            ra0 = *(const float4*)(A + (size_t)(k0 + k)      * lda + bm + c);
            ra1 = *(const float4*)(A + (size_t)(k0 + k + 16) * lda + bm + c);
        }
    };
    auto stA = [&](float* As) {
        if constexpr (AM == 0) {
            int r = tid >> 3, c = (tid & 7) * 4;
            As[(c+0)*SROW + r] = ra0.x; As[(c+1)*SROW + r] = ra0.y;
            As[(c+2)*SROW + r] = ra0.z; As[(c+3)*SROW + r] = ra0.w;
            As[(c+0)*SROW + r+32] = ra1.x; As[(c+1)*SROW + r+32] = ra1.y;
            As[(c+2)*SROW + r+32] = ra1.z; As[(c+3)*SROW + r+32] = ra1.w;
        } else {
            int k = tid >> 4, c = (tid & 15) * 4;
            *(float4*)(As + k*SROW + c)      = ra0;
            *(float4*)(As + (k+16)*SROW + c) = ra1;
        }
    };
    auto ldB = [&](int k0) {
        if constexpr (BM == 1) {
            int r = tid >> 3, c = (tid & 7) * 4;
            rb0 = *(const float4*)(B + (size_t)(bn + r)      * ldb + k0 + c);
            rb1 = *(const float4*)(B + (size_t)(bn + r + 32) * ldb + k0 + c);
        } else {
            int k = tid >> 4, c = (tid & 15) * 4;
            rb0 = *(const float4*)(B + (size_t)(k0 + k)      * ldb + bn + c);
            rb1 = *(const float4*)(B + (size_t)(k0 + k + 16) * ldb + bn + c);
        }
    };
    auto stB = [&](float* Bs) {
        if constexpr (BM == 1) {
            int r = tid >> 3, c = (tid & 7) * 4;
            Bs[(c+0)*SROW + r] = rb0.x; Bs[(c+1)*SROW + r] = rb0.y;
            Bs[(c+2)*SROW + r] = rb0.z; Bs[(c+3)*SROW + r] = rb0.w;
            Bs[(c+0)*SROW + r+32] = rb1.x; Bs[(c+1)*SROW + r+32] = rb1.y;
            Bs[(c+2)*SROW + r+32] = rb1.z; Bs[(c+3)*SROW + r+32] = rb1.w;
        } else {
            int k = tid >> 4, c = (tid & 15) * 4;
            *(float4*)(Bs + k*SROW + c)      = rb0;
            *(float4*)(Bs + (k+16)*SROW + c) = rb1;
        }
    };

    float acc[4][4] = {};
    ldA(0); ldB(0);
    int s = 0;
    for (int k0 = 0; k0 < K; k0 += 32) {
        float* As = sbuf + s * STAGE2;
        float* Bs = As + 32 * SROW;
        stA(As); stB(Bs);
        __syncthreads();
        if (k0 + 32 < K) { ldA(k0 + 32); ldB(k0 + 32); }
#pragma unroll
        for (int kk = 0; kk < 32; kk++) {
            float4 a = *(float4*)(As + kk*SROW + ty*4);
            float4 b = *(float4*)(Bs + kk*SROW + tx*4);
            acc[0][0] = fmaf(a.x, b.x, acc[0][0]); acc[0][1] = fmaf(a.x, b.y, acc[0][1]);
            acc[0][2] = fmaf(a.x, b.z, acc[0][2]); acc[0][3] = fmaf(a.x, b.w, acc[0][3]);
            acc[1][0] = fmaf(a.y, b.x, acc[1][0]); acc[1][1] = fmaf(a.y, b.y, acc[1][1]);
            acc[1][2] = fmaf(a.y, b.z, acc[1][2]); acc[1][3] = fmaf(a.y, b.w, acc[1][3]);
            acc[2][0] = fmaf(a.z, b.x, acc[2][0]); acc[2][1] = fmaf(a.z, b.y, acc[2][1]);
            acc[2][2] = fmaf(a.z, b.z, acc[2][2]); acc[2][3] = fmaf(a.z, b.w, acc[2][3]);
            acc[3][0] = fmaf(a.w, b.x, acc[3][0]); acc[3][1] = fmaf(a.w, b.y, acc[3][1]);
            acc[3][2] = fmaf(a.w, b.z, acc[3][2]); acc[3][3] = fmaf(a.w, b.w, acc[3][3]);
        }
        s ^= 1;
    }

    float4 bb = make_float4(0.f, 0.f, 0.f, 0.f);
    if (bias) bb = *(const float4*)(bias + bn + tx * 4);
#pragma unroll
    for (int i = 0; i < 4; i++) {
        int m = bm + ty * 4 + i;
        float4 v;
        v.x = acc[i][0] + bb.x; v.y = acc[i][1] + bb.y;
        v.z = acc[i][2] + bb.z; v.w = acc[i][3] + bb.w;
        *(float4*)(C + (size_t)m * ldc + bn + tx * 4) = v;
    }
}

// ---------------------------------------------------------------------------
// tile3 double-buffered: 128x64, BK=32, 8x4/thread, 1 barrier per chunk.
// ---------------------------------------------------------------------------
template <int BM>
__device__ __forceinline__ void gemm_tile3(
    const float* __restrict__ A, const float* __restrict__ B,
    const float* __restrict__ bias, float* __restrict__ C,
    int bm, int bn, int K, int lda, int ldb, int ldc, float* sbuf)
{
    const int tid = threadIdx.x;
    const int tx = tid & 15, ty = tid >> 4;
    const int m0 = ty * 8, n0 = tx * 4;

    float4 ra[4], rb[2];
    auto ldA = [&](int k0) {
#pragma unroll
        for (int p = 0; p < 4; p++) {
            int idx = tid + p * 256;
            int r = idx >> 3, c4 = (idx & 7) * 4;
            ra[p] = *(const float4*)(A + (size_t)(bm + r) * lda + k0 + c4);
        }
    };
    auto stA = [&](float* As) {
#pragma unroll
        for (int p = 0; p < 4; p++) {
            int idx = tid + p * 256;
            int r = idx >> 3, c4 = (idx & 7) * 4;
            As[(c4+0)*AR3 + r] = ra[p].x; As[(c4+1)*AR3 + r] = ra[p].y;
            As[(c4+2)*AR3 + r] = ra[p].z; As[(c4+3)*AR3 + r] = ra[p].w;
        }
    };
    auto ldB = [&](int k0) {
        if constexpr (BM == 1) {
#pragma unroll
            for (int p = 0; p < 2; p++) {
                int idx = tid + p * 256;
                int r = idx >> 3, c4 = (idx & 7) * 4;
                rb[p] = *(const float4*)(B + (size_t)(bn + r) * ldb + k0 + c4);
            }
        } else {
#pragma unroll
            for (int p = 0; p < 2; p++) {
                int idx = tid + p * 256;
                int k = idx >> 4, c4 = (idx & 15) * 4;
                rb[p] = *(const float4*)(B + (size_t)(k0 + k) * ldb + bn + c4);
            }
        }
    };
    auto stB = [&](float* Bs) {
        if constexpr (BM == 1) {
#pragma unroll
            for (int p = 0; p < 2; p++) {
                int idx = tid + p * 256;
                int r = idx >> 3, c4 = (idx & 7) * 4;
                Bs[(c4+0)*BR3 + r] = rb[p].x; Bs[(c4+1)*BR3 + r] = rb[p].y;
                Bs[(c4+2)*BR3 + r] = rb[p].z; Bs[(c4+3)*BR3 + r] = rb[p].w;
            }
        } else {
#pragma unroll
            for (int p = 0; p < 2; p++) {
                int idx = tid + p * 256;
                int k = idx >> 4, c4 = (idx & 15) * 4;
                *(float4*)(Bs + k*BR3 + c4) = rb[p];
            }
        }
    };

    float acc[8][4] = {};
    ldA(0); ldB(0);
    int s = 0;
    for (int k0 = 0; k0 < K; k0 += 32) {
        float* As = sbuf + s * STAGE3;
        float* Bs = As + 32 * AR3;
        stA(As); stB(Bs);
        __syncthreads();
        if (k0 + 32 < K) { ldA(k0 + 32); ldB(k0 + 32); }
#pragma unroll
        for (int kk = 0; kk < 32; kk++) {
            float4 a0 = *(float4*)(As + kk*AR3 + m0);
            float4 a1 = *(float4*)(As + kk*AR3 + m0 + 4);
            float4 b  = *(float4*)(Bs + kk*BR3 + n0);
            acc[0][0] = fmaf(a0.x,b.x,acc[0][0]); acc[0][1] = fmaf(a0.x,b.y,acc[0][1]);
            acc[0][2] = fmaf(a0.x,b.z,acc[0][2]); acc[0][3] = fmaf(a0.x,b.w,acc[0][3]);
            acc[1][0] = fmaf(a0.y,b.x,acc[1][0]); acc[1][1] = fmaf(a0.y,b.y,acc[1][1]);
            acc[1][2] = fmaf(a0.y,b.z,acc[1][2]); acc[1][3] = fmaf(a0.y,b.w,acc[1][3]);
            acc[2][0] = fmaf(a0.z,b.x,acc[2][0]); acc[2][1] = fmaf(a0.z,b.y,acc[2][1]);
            acc[2][2] = fmaf(a0.z,b.z,acc[2][2]); acc[2][3] = fmaf(a0.z,b.w,acc[2][3]);
            acc[3][0] = fmaf(a0.w,b.x,acc[3][0]); acc[3][1] = fmaf(a0.w,b.y,acc[3][1]);
            acc[3][2] = fmaf(a0.w,b.z,acc[3][2]); acc[3][3] = fmaf(a0.w,b.w,acc[3][3]);
            acc[4][0] = fmaf(a1.x,b.x,acc[4][0]); acc[4][1] = fmaf(a1.x,b.y,acc[4][1]);
            acc[4][2] = fmaf(a1.x,b.z,acc[4][2]); acc[4][3] = fmaf(a1.x,b.w,acc[4][3]);
            acc[5][0] = fmaf(a1.y,b.x,acc[5][0]); acc[5][1] = fmaf(a1.y,b.y,acc[5][1]);
            acc[5][2] = fmaf(a1.y,b.z,acc[5][2]); acc[5][3] = fmaf(a1.y,b.w,acc[5][3]);
            acc[6][0] = fmaf(a1.z,b.x,acc[6][0]); acc[6][1] = fmaf(a1.z,b.y,acc[6][1]);
            acc[6][2] = fmaf(a1.z,b.z,acc[6][2]); acc[6][3] = fmaf(a1.z,b.w,acc[6][3]);
            acc[7][0] = fmaf(a1.w,b.x,acc[7][0]); acc[7][1] = fmaf(a1.w,b.y,acc[7][1]);
            acc[7][2] = fmaf(a1.w,b.z,acc[7][2]); acc[7][3] = fmaf(a1.w,b.w,acc[7][3]);
        }
        s ^= 1;
    }

    float4 bb = make_float4(0.f, 0.f, 0.f, 0.f);
    if (bias) bb = *(const float4*)(bias + bn + n0);
#pragma unroll
    for (int i = 0; i < 8; i++) {
        int m = bm + m0 + i;
        float4 v;
        v.x = acc[i][0] + bb.x; v.y = acc[i][1] + bb.y;
        v.z = acc[i][2] + bb.z; v.w = acc[i][3] + bb.w;
        *(float4*)(C + (size_t)m * ldc + bn + n0) = v;
    }
}

// ---------------------------------------------------------------------------
// K1: KEY (tile2, 60), QRY (tile3, 32), QQ (tile3, 32), BFQ (tile2, 16), bias.
// ---------------------------------------------------------------------------
__global__ __launch_bounds__(256)
void k1_proj(const float* __restrict__ memkey, const float* __restrict__ h,
             const float* __restrict__ key_w,  const float* __restrict__ key_b,
             const float* __restrict__ query_w,const float* __restrict__ query_b,
             const float* __restrict__ qq_w,   const float* __restrict__ qq_b,
             const float* __restrict__ kq_w,   const float* __restrict__ kq_b,
             const float* __restrict__ proto_w,const float* __restrict__ proto_b,
             float* __restrict__ KEY, float* __restrict__ QRY, float* __restrict__ QQ,
             float* __restrict__ BFQ, float* __restrict__ BF)
{
    extern __shared__ __align__(16) float dbuf[];
    const int b = blockIdx.x;
    if (b < 60) {
        gemm_tile2<0,1>(memkey, key_w, key_b, KEY, (b/4)*64, (b%4)*64, HID, HID, HID, HID, dbuf);
    } else if (b < 92) {
        int i = b - 60;
        gemm_tile3<1>(h, query_w, query_b, QRY, (i/4)*128, (i%4)*64, HID, HID, HID, HID, dbuf);
    } else if (b < 124) {
        int i = b - 92;
        gemm_tile3<1>(h, qq_w, qq_b, QQ, (i/4)*128, (i%4)*64, HID, HID, HID, HID, dbuf);
    } else if (b < 140) {
        int i = b - 124;
        gemm_tile2<1,1>(kq_w, proto_w, nullptr, BFQ, (i/4)*64, (i%4)*64, HID, HID, 2*HID, HID, dbuf);
    } else {
        const int t = threadIdx.x;
        float s2 = proto_b[t];
        for (int c = 0; c < HID; c++)
            s2 = fmaf(kq_b[c], proto_w[(size_t)t * (2*HID) + c], s2);
        BF[t] = s2;
        if (t < NCLS) g_cnt[t] = 0;
    }
}

// ---------------------------------------------------------------------------
// K2: SC1 (tile3, 120), QHAT (tile3 BM=0, 32), KEYP (tile2, 60). grid 212.
// ---------------------------------------------------------------------------
__global__ __launch_bounds__(256)
void k2_score1(const float* __restrict__ QRY, const float* __restrict__ KEY,
               const float* __restrict__ QQ,  const float* __restrict__ kq_w,
               const float* __restrict__ proto_w,
               float* __restrict__ SC1, float* __restrict__ QHAT, float* __restrict__ KEYP)
{
    extern __shared__ __align__(16) float dbuf[];
    const int b = blockIdx.x;
    if (b < 120) {
        gemm_tile3<1>(QRY, KEY, nullptr, SC1, (b/15)*128, (b%15)*64, HID, HID, HID, NKEYS, dbuf);
    } else if (b < 152) {
        int i = b - 120;
        gemm_tile3<0>(QQ, kq_w, nullptr, QHAT, (i/4)*128, (i%4)*64, HID, HID, HID, HID, dbuf);
    } else {
        int i = b - 152;
        gemm_tile2<0,1>(KEY, proto_w + HID, nullptr, KEYP, (i/4)*64, (i%4)*64, HID, HID, 2*HID, HID, dbuf);
    }
}

// ---------------------------------------------------------------------------
// K3: warp-per-row top-5 via register lists + shfl merges. Records g_topc.
// ---------------------------------------------------------------------------
__global__ __launch_bounds__(256)
void k3_topk1(const float* __restrict__ SC1, const float* __restrict__ KEYP,
              float* __restrict__ OUTM)
{
    const int lane = threadIdx.x & 31;
    const int n = blockIdx.x * 8 + (threadIdx.x >> 5);

    float lv[TOPK]; int li[TOPK];
#pragma unroll
    for (int j = 0; j < TOPK; j++) { lv[j] = -INFINITY; li[j] = 0x7fffffff; }

    const float* row = SC1 + (size_t)n * NKEYS;
#pragma unroll 6
    for (int i = 0; i < NKEYS / 32; i++) {
        int idx = i * 32 + lane;
        float v = row[idx];
        if (v > lv[TOPK-1]) {
            int p = TOPK - 1;
            while (p > 0 && v > lv[p-1]) { lv[p] = lv[p-1]; li[p] = li[p-1]; p--; }
            lv[p] = v; li[p] = idx;
        }
    }

#pragma unroll
    for (int off = 16; off >= 1; off >>= 1) {
        float pv[TOPK]; int pi[TOPK];
#pragma unroll
        for (int j = 0; j < TOPK; j++) {
            pv[j] = __shfl_xor_sync(0xffffffffu, lv[j], off);
            pi[j] = __shfl_xor_sync(0xffffffffu, li[j], off);
        }
        float ov[TOPK]; int oi[TOPK];
        int pa = 0, pb = 0;
#pragma unroll
        for (int j = 0; j < TOPK; j++) {
            bool ta = (lv[pa] > pv[pb]) || (lv[pa] == pv[pb] && li[pa] < pi[pb]);
            if (ta) { ov[j] = lv[pa]; oi[j] = li[pa]; pa++; }
            else    { ov[j] = pv[pb]; oi[j] = pi[pb]; pb++; }
        }
#pragma unroll
        for (int j = 0; j < TOPK; j++) { lv[j] = ov[j]; li[j] = oi[j]; }
    }

    float w[TOPK];
    float mx = lv[0], den = 0.f;
#pragma unroll
    for (int j = 0; j < TOPK; j++) { w[j] = expf(lv[j] - mx); den += w[j]; }
    float dinv = 1.f / den;
#pragma unroll
    for (int j = 0; j < TOPK; j++) w[j] *= dinv;

    if (lane == 0) {
#pragma unroll
        for (int j = 0; j < TOPK; j++) {
            int c = li[j] / DCS;
            g_topc[n * TOPK + j] = c * CPB;
            int p = atomicAdd(&g_cnt[c], 1);
            g_pairs[c * CAP + p] = n * 8 + j;
        }
    }

#pragma unroll
    for (int i = 0; i < HID / 32; i++) {
        int d = i * 32 + lane;
        float acc = 0.f;
#pragma unroll
        for (int j = 0; j < TOPK; j++)
            acc = fmaf(w[j], KEYP[(size_t)li[j] * HID + d], acc);
        OUTM[(size_t)n * HID + d] = acc;
    }
}

// ---------------------------------------------------------------------------
// K4 v6: class-batched scoring GEMM, split-K(8), B resident. grid (60, 24).
// ---------------------------------------------------------------------------
__global__ __launch_bounds__(256)
void k4_score2(const float* __restrict__ QHAT, const float* __restrict__ rawq,
               float* __restrict__ SC2)
{
    __shared__ float Bsh[32][85];
    __shared__ __align__(16) float As[32][68];
    __shared__ int   spn[64], spj[64];

    const int c = blockIdx.x, tid = threadIdx.x;
    const int kh = blockIdx.y & 7;
    const int ty0 = blockIdx.y >> 3;
    const int kbase = kh * 32;
    const int cnt = g_cnt[c];
    const int tm = tid >> 4, tn = tid & 15;
    const float* rbase = rawq + (size_t)c * CPB * HID;
    float* outb = SC2 + (size_t)kh * NROWS * CAND;

#pragma unroll
    for (int p = 0; p < 3; p++) {
        int idx = tid + p * 256;
        if (idx < CPB * 8) {
            int q = idx >> 3, c4 = (idx & 7) * 4;
            float4 v = *(const float4*)(rbase + (size_t)q * HID + kbase + c4);
            Bsh[c4+0][q] = v.x; Bsh[c4+1][q] = v.y;
            Bsh[c4+2][q] = v.z; Bsh[c4+3][q] = v.w;
        }
    }

    const int am0 = tid >> 3, ac0 = (tid & 7) * 4;
    const int am1 = (tid + 256) >> 3, ac1 = ((tid + 256) & 7) * 4;

    for (int tt = ty0; tt * 64 < cnt; tt += 3) {
        const int m0 = tt * 64;
        __syncthreads();
        if (tid < 64) {
            int mi = m0 + tid;
            int pm = g_pairs[c * CAP + (mi < cnt ? mi : m0)];
            spn[tid] = pm >> 3; spj[tid] = pm & 7;
        }
        __syncthreads();

        {
            float4 rA0 = *(const float4*)(QHAT + (size_t)spn[am0] * HID + kbase + ac0);
            float4 rA1 = *(const float4*)(QHAT + (size_t)spn[am1] * HID + kbase + ac1);
            As[ac0+0][am0] = rA0.x; As[ac0+1][am0] = rA0.y;
            As[ac0+2][am0] = rA0.z; As[ac0+3][am0] = rA0.w;
            As[ac1+0][am1] = rA1.x; As[ac1+1][am1] = rA1.y;
            As[ac1+2][am1] = rA1.z; As[ac1+3][am1] = rA1.w;
        }
        __syncthreads();

        float acc[4][5] = {};
#pragma unroll
        for (int kk = 0; kk < 32; kk++) {
            float4 a = *(float4*)&As[kk][tm * 4];
            float b0 = Bsh[kk][tn*5+0], b1 = Bsh[kk][tn*5+1], b2 = Bsh[kk][tn*5+2];
            float b3 = Bsh[kk][tn*5+3], b4 = Bsh[kk][tn*5+4];
            acc[0][0] = fmaf(a.x,b0,acc[0][0]); acc[0][1] = fmaf(a.x,b1,acc[0][1]);
            acc[0][2] = fmaf(a.x,b2,acc[0][2]); acc[0][3] = fmaf(a.x,b3,acc[0][3]);
            acc[0][4] = fmaf(a.x,b4,acc[0][4]);
            acc[1][0] = fmaf(a.y,b0,acc[1][0]); acc[1][1] = fmaf(a.y,b1,acc[1][1]);
            acc[1][2] = fmaf(a.y,b2,acc[1][2]); acc[1][3] = fmaf(a.y,b3,acc[1][3]);
            acc[1][4] = fmaf(a.y,b4,acc[1][4]);
            acc[2][0] = fmaf(a.z,b0,acc[2][0]); acc[2][1] = fmaf(a.z,b1,acc[2][1]);
            acc[2][2] = fmaf(a.z,b2,acc[2][2]); acc[2][3] = fmaf(a.z,b3,acc[2][3]);
            acc[2][4] = fmaf(a.z,b4,acc[2][4]);
            acc[3][0] = fmaf(a.w,b0,acc[3][0]); acc[3][1] = fmaf(a.w,b1,acc[3][1]);
            acc[3][2] = fmaf(a.w,b2,acc[3][2]); acc[3][3] = fmaf(a.w,b3,acc[3][3]);
            acc[3][4] = fmaf(a.w,b4,acc[3][4]);
        }
#pragma unroll
        for (int i = 0; i < 4; i++) {
            int m = tm * 4 + i;
            if (m0 + m < cnt) {
                float* dst = outb + (size_t)spn[m] * CAND + spj[m] * CPB + tn * 5;
#pragma unroll
                for (int jq = 0; jq < 5; jq++) dst[jq] = acc[i][jq];
            }
        }
    }
}

// ---------------------------------------------------------------------------
// K56 v2: fused select + weighted gather-sum with sync-lean primitives.
// Sort: hybrid bitonic — regs + shfl (j<=16), in-thread (j=256),
//       smem only for j in {32,64,128} (9 stages). Identical network.
// Scans: ballot/popc warp scans + 16-wide serial prefix. Identical positions.
// ---------------------------------------------------------------------------
__global__ __launch_bounds__(256)
void k56_select_wsum(const float* __restrict__ SC2, const float* __restrict__ rawq,
                     float* __restrict__ QSUM)
{
    __shared__ float sb[512];
    __shared__ float rr[256];
    __shared__ int   ii[256];
    __shared__ int   wsum[16];
    __shared__ int   wpre[16];
    __shared__ int   selrow[TOPKQ];
    __shared__ float selw[TOPKQ];
    __shared__ int   cls[TOPK];
    __shared__ float s_den;
    __shared__ int   s_G;

    const int n = blockIdx.x, tid = threadIdx.x;
    const int lane = tid & 31, w = tid >> 5;

    if (tid < TOPK) cls[tid] = g_topc[n * TOPK + tid];
    float v0 = 0.f, v1 = 0.f;
#pragma unroll
    for (int s = 0; s < KSPLIT; s++) {
        const float* slab = SC2 + (size_t)s * NROWS * CAND + (size_t)n * CAND;
        v0 += slab[tid];
        if (tid < CAND - 256) v1 += slab[tid + 256];
    }
    const bool has1 = (tid < CAND - 256);

    // ---- hybrid bitonic sort (ascending) of a value copy ----
    float e0 = v0;
    float e1 = has1 ? v1 : -INFINITY;

    auto cas_shfl = [&](int k, int j) {
        float p0 = __shfl_xor_sync(0xffffffffu, e0, j);
        float p1 = __shfl_xor_sync(0xffffffffu, e1, j);
        bool lower = ((tid & j) == 0);
        bool asc0 = ((tid & k) == 0);
        bool asc1 = (((tid + 256) & k) == 0);
        e0 = (lower == asc0) ? fminf(e0, p0) : fmaxf(e0, p0);
        e1 = (lower == asc1) ? fminf(e1, p1) : fmaxf(e1, p1);
    };
    auto cas_smem = [&](int k, int j) {
        sb[tid] = e0; sb[tid + 256] = e1;
        __syncthreads();
        float p0 = sb[tid ^ j];
        float p1 = sb[(tid ^ j) + 256];
        bool lower = ((tid & j) == 0);
        bool asc0 = ((tid & k) == 0);
        bool asc1 = (((tid + 256) & k) == 0);
        e0 = (lower == asc0) ? fminf(e0, p0) : fmaxf(e0, p0);
        e1 = (lower == asc1) ? fminf(e1, p1) : fmaxf(e1, p1);
        __syncthreads();
    };

#pragma unroll
    for (int k = 2; k <= 32; k <<= 1)
#pragma unroll
        for (int j = k >> 1; j > 0; j >>= 1) cas_shfl(k, j);
    cas_smem(64, 32);
#pragma unroll
    for (int j = 16; j > 0; j >>= 1) cas_shfl(64, j);
    cas_smem(128, 64); cas_smem(128, 32);
#pragma unroll
    for (int j = 16; j > 0; j >>= 1) cas_shfl(128, j);
    cas_smem(256, 128); cas_smem(256, 64); cas_smem(256, 32);
#pragma unroll
    for (int j = 16; j > 0; j >>= 1) cas_shfl(256, j);
    { float lo = fminf(e0, e1), hi = fmaxf(e0, e1); e0 = lo; e1 = hi; }  // k=512, j=256
    cas_smem(512, 128); cas_smem(512, 64); cas_smem(512, 32);
#pragma unroll
    for (int j = 16; j > 0; j >>= 1) cas_shfl(512, j);

    sb[tid] = e0; sb[tid + 256] = e1;
    __syncthreads();
    const float T  = sb[512 - TOPKQ];
    const float mx = sb[511];

    // ---- G (strict-greater count) + softmax denominator ----
    {
        int cnt = 0; float den = 0.f;
        if (v0 > T)          { cnt++; den += expf(v0 - mx); }
        if (has1 && v1 > T)  { cnt++; den += expf(v1 - mx); }
        rr[tid] = den; ii[tid] = cnt;
    }
    __syncthreads();
    for (int off = 128; off > 0; off >>= 1) {
        if (tid < off) { rr[tid] += rr[tid + off]; ii[tid] += ii[tid + off]; }
        __syncthreads();
    }
    if (tid == 0) {
        s_G = ii[0];
        s_den = rr[0] + (float)(TOPKQ - ii[0]) * expf(T - mx);
    }
    __syncthreads();
    const int   G = s_G;
    const float dinv = 1.f / s_den;
    const unsigned leq = 0xffffffffu >> (31 - lane);

    // ---- scan 1: strict-greater -> positions [0, G) ----
    {
        int f0 = (v0 > T) ? 1 : 0;
        int f1 = (has1 && v1 > T) ? 1 : 0;
        unsigned m0 = __ballot_sync(0xffffffffu, f0);
        unsigned m1 = __ballot_sync(0xffffffffu, f1);
        int p0 = __popc(m0 & leq);
        int p1 = __popc(m1 & leq);
        if (lane == 0) { wsum[w] = __popc(m0); wsum[8 + w] = __popc(m1); }
        __syncthreads();
        if (tid == 0) {
            int acc = 0;
#pragma unroll
            for (int i = 0; i < 16; i++) { wpre[i] = acc; acc += wsum[i]; }
        }
        __syncthreads();
        if (f0) {
            int p = wpre[w] + p0 - 1;
            selrow[p] = cls[tid / CPB] + (tid % CPB);
            selw[p]   = expf(v0 - mx) * dinv;
        }
        if (f1) {
            int m = tid + 256;
            int p = wpre[8 + w] + p1 - 1;
            selrow[p] = cls[m / CPB] + (m % CPB);
            selw[p]   = expf(v1 - mx) * dinv;
        }
    }
    __syncthreads();

    // ---- scan 2: ties -> positions [G, TOPKQ) in index order ----
    {
        int f0 = (v0 == T) ? 1 : 0;
        int f1 = (has1 && v1 == T) ? 1 : 0;
        unsigned m0 = __ballot_sync(0xffffffffu, f0);
        unsigned m1 = __ballot_sync(0xffffffffu, f1);
        int p0 = __popc(m0 & leq);
        int p1 = __popc(m1 & leq);
        if (lane == 0) { wsum[w] = __popc(m0); wsum[8 + w] = __popc(m1); }
        __syncthreads();
        if (tid == 0) {
            int acc = 0;
#pragma unroll
            for (int i = 0; i < 16; i++) { wpre[i] = acc; acc += wsum[i]; }
        }
        __syncthreads();
        const float wT = expf(T - mx) * dinv;
        if (f0) {
            int r = wpre[w] + p0 - 1;
            if (r < TOPKQ - G) {
                selrow[G + r] = cls[tid / CPB] + (tid % CPB);
                selw[G + r]   = wT;
            }
        }
        if (f1) {
            int m = tid + 256;
            int r = wpre[8 + w] + p1 - 1;
            if (r < TOPKQ - G) {
                selrow[G + r] = cls[m / CPB] + (m % CPB);
                selw[G + r]   = wT;
            }
        }
    }
    __syncthreads();

    // ---- weighted sum of selected raw rows (thread = dim, coalesced) ----
    float acc0 = 0.f, acc1 = 0.f, acc2 = 0.f, acc3 = 0.f;
    for (int p = 0; p < TOPKQ; p += 4) {
        acc0 = fmaf(selw[p + 0], rawq[(size_t)selrow[p + 0] * HID + tid], acc0);
        acc1 = fmaf(selw[p + 1], rawq[(size_t)selrow[p + 1] * HID + tid], acc1);
        acc2 = fmaf(selw[p + 2], rawq[(size_t)selrow[p + 2] * HID + tid], acc2);
        acc3 = fmaf(selw[p + 3], rawq[(size_t)selrow[p + 3] * HID + tid], acc3);
    }
    QSUM[(size_t)n * HID + tid] = (acc0 + acc1) + (acc2 + acc3);
}

// ---------------------------------------------------------------------------
// K7: out = QSUM @ BfQ + OUTM + bf.  tile 64m x 32n, grid (8, 16)
// ---------------------------------------------------------------------------
__global__ __launch_bounds__(256)
void k7_out(const float* __restrict__ QSUM, const float* __restrict__ BFQ,
            const float* __restrict__ OUTM, const float* __restrict__ BF,
            float* __restrict__ out)
{
    __shared__ float As[32][65];
    __shared__ float Bsh[32][36];
    const int tid = threadIdx.x;
    const int bm = blockIdx.y * 64, bn = blockIdx.x * 32;
    const int ty = tid >> 3, tx = tid & 7;

    float acc[2][4] = {};
    for (int k0 = 0; k0 < HID; k0 += 32) {
        __syncthreads();
        {
            int r = tid >> 3, c4 = (tid & 7) * 4;
#pragma unroll
            for (int h = 0; h < 2; h++) {
                int m = bm + r + h * 32;
                float4 v = *(const float4*)(QSUM + (size_t)m * HID + k0 + c4);
                As[c4+0][r + h*32] = v.x; As[c4+1][r + h*32] = v.y;
                As[c4+2][r + h*32] = v.z; As[c4+3][r + h*32] = v.w;
            }
        }
        {
            int k = tid >> 3, c4 = (tid & 7) * 4;
            *(float4*)&Bsh[k][c4] = *(const float4*)(BFQ + (size_t)(k0 + k) * HID + bn + c4);
        }
        __syncthreads();
#pragma unroll
        for (int kk = 0; kk < 32; kk++) {
            float a0 = As[kk][ty*2 + 0], a1 = As[kk][ty*2 + 1];
            float4 b = *(float4*)&Bsh[kk][tx*4];
            acc[0][0] = fmaf(a0,b.x,acc[0][0]); acc[0][1] = fmaf(a0,b.y,acc[0][1]);
            acc[0][2] = fmaf(a0,b.z,acc[0][2]); acc[0][3] = fmaf(a0,b.w,acc[0][3]);
            acc[1][0] = fmaf(a1,b.x,acc[1][0]); acc[1][1] = fmaf(a1,b.y,acc[1][1]);
            acc[1][2] = fmaf(a1,b.z,acc[1][2]); acc[1][3] = fmaf(a1,b.w,acc[1][3]);
        }
    }

    float4 bb = *(const float4*)(BF + bn + tx * 4);
#pragma unroll
    for (int i = 0; i < 2; i++) {
        int m = bm + ty * 2 + i;
        float4 om = *(const float4*)(OUTM + (size_t)m * HID + bn + tx * 4);
        float4 v;
        v.x = acc[i][0] + bb.x + om.x; v.y = acc[i][1] + bb.y + om.y;
        v.z = acc[i][2] + bb.z + om.z; v.w = acc[i][3] + bb.w + om.w;
        *(float4*)(out + (size_t)m * HID + bn + tx * 4) = v;
    }
}

// ---------------------------------------------------------------------------
extern "C" void kernel_launch(void* const* d_in, const int* in_sizes, int n_in,
                              void* d_out, int out_size)
{
    const int sh = (n_in >= 15) ? 0 : 1;
    const float* h          = (const float*)d_in[0];
    const float* memory_key = (const float*)d_in[3 - sh];
    const float* queue_key  = (const float*)d_in[4 - sh];
    const float* key_w      = (const float*)d_in[5 - sh];
    const float* key_b      = (const float*)d_in[6 - sh];
    const float* query_w    = (const float*)d_in[7 - sh];
    const float* query_b    = (const float*)d_in[8 - sh];
    const float* kq_w       = (const float*)d_in[9 - sh];
    const float* kq_b       = (const float*)d_in[10 - sh];
    const float* qq_w       = (const float*)d_in[11 - sh];
    const float* qq_b       = (const float*)d_in[12 - sh];
    const float* proto_w    = (const float*)d_in[13 - sh];
    const float* proto_b    = (const float*)d_in[14 - sh];
    float* out = (float*)d_out;

    void* sp = nullptr; cudaGetSymbolAddress(&sp, g_scratch);
    float* S = (float*)sp;
    float* KEY  = S + OFF_KEY;
    float* QRY  = S + OFF_QRY;
    float* QQ   = S + OFF_QQ;
    float* QHAT = S + OFF_QHAT;
    float* KEYP = S + OFF_KEYP;
    float* SC1  = S + OFF_SC1;
    float* SC2  = S + OFF_SC2;
    float* QSUM = S + OFF_QSUM;
    float* OUTM = S + OFF_OUTM;
    float* BFQ  = S + OFF_BFQ;
    float* BF   = S + OFF_BF;

    cudaFuncSetAttribute(k1_proj,   cudaFuncAttributeMaxDynamicSharedMemorySize, DBUF_BYTES);
    cudaFuncSetAttribute(k2_score1, cudaFuncAttributeMaxDynamicSharedMemorySize, DBUF_BYTES);

    k1_proj<<<141, 256, DBUF_BYTES>>>(memory_key, h, key_w, key_b, query_w, query_b,
                                      qq_w, qq_b, kq_w, kq_b, proto_w, proto_b,
                                      KEY, QRY, QQ, BFQ, BF);
    k2_score1<<<212, 256, DBUF_BYTES>>>(QRY, KEY, QQ, kq_w, proto_w, SC1, QHAT, KEYP);
    k3_topk1<<<NROWS / 8, 256>>>(SC1, KEYP, OUTM);
    k4_score2<<<dim3(60, 24), 256>>>(QHAT, queue_key, SC2);
    k56_select_wsum<<<NROWS, 256>>>(SC2, queue_key, QSUM);
    k7_out<<<dim3(8, 16), 256>>>(QSUM, BFQ, OUTM, BF, out);
}